// round 11
// baseline (speedup 1.0000x reference)
#include <cuda_runtime.h>
#include <cuda_fp16.h>
#include <cstdint>

// ---------------------------------------------------------------------------
// SEMMBlock: spiking-router MoE transformer block.
// B=4 S=1024 D=512 E=8 F=2048 H=4 dh=128.
// Round 11: hgemm BK=64 2-stage (half the barriers), router/lists on aux
// stream overlapping conversions + dense K/V GEMM, bias pack merged into
// the one-shot conversion kernel.
// ---------------------------------------------------------------------------

#define B_  4
#define S_  1024
#define D_  512
#define E_  8
#define F_  2048
#define H_  4
#define DH_ 128
#define N_  (B_ * S_)
#define SEGS (E_ * B_)
#define LN_EPS 1e-5f

#define DD_  (D_ * D_)
#define ND_  ((long long)N_ * D_)
#define SD_  ((long long)S_ * D_)
#define SF_  ((long long)S_ * F_)

// ------------------------- scratch (device globals) ------------------------
__device__ float  g_rw[N_ * E_];
__device__ int    g_cnt[SEGS];
__device__ int    g_idx[SEGS * S_];
__device__ int    g_pos[N_ * E_];
__device__ float  g_bkv[E_ * 2 * D_];
__device__ __half g_xh[N_ * D_];
__device__ __half g_wqh[E_ * DD_];             // [e][K][N] fp16 (untransposed)
__device__ __half g_wkvh[(size_t)E_ * 2 * DD_];// [e][{k,v}][K][N]
__device__ __half g_woh[E_ * DD_];
__device__ __half g_w1h[(size_t)E_ * D_ * F_];
__device__ __half g_w2h[(size_t)E_ * F_ * D_];
__device__ __half g_kvh[(size_t)E_ * 2 * N_ * D_];
__device__ __half g_qh[(size_t)SEGS * S_ * D_];
__device__ __half g_ogh[(size_t)SEGS * S_ * D_];
__device__ __half g_hgh[(size_t)SEGS * S_ * D_];
__device__ __half g_f1h[(size_t)SEGS * S_ * F_];
__device__ float  g_t1[(size_t)SEGS * S_ * D_];
__device__ float  g_hg[(size_t)SEGS * S_ * D_];
__device__ float  g_f2[(size_t)SEGS * S_ * D_];

// ------------------------------ helpers -------------------------------------
__device__ __forceinline__ void cp_async16(uint32_t smem, const void* gptr) {
    asm volatile("cp.async.cg.shared.global [%0], [%1], 16;\n" :: "r"(smem), "l"(gptr));
}
__device__ __forceinline__ void cp_commit() {
    asm volatile("cp.async.commit_group;\n");
}
__device__ __forceinline__ void cp_wait0() {
    asm volatile("cp.async.wait_group 0;\n");
}
__device__ __forceinline__ void mma_f16(float* c, unsigned a0, unsigned a1,
                                        unsigned a2, unsigned a3,
                                        unsigned b0, unsigned b1) {
    asm volatile(
        "mma.sync.aligned.m16n8k16.row.col.f32.f16.f16.f32 "
        "{%0,%1,%2,%3}, {%4,%5,%6,%7}, {%8,%9}, {%0,%1,%2,%3};\n"
        : "+f"(c[0]), "+f"(c[1]), "+f"(c[2]), "+f"(c[3])
        : "r"(a0), "r"(a1), "r"(a2), "r"(a3), "r"(b0), "r"(b1));
}
__device__ __forceinline__ unsigned h2pack(float x, float y) {
    __half2 h = __floats2half2_rn(x, y);
    return *(unsigned*)&h;
}
__device__ __forceinline__ float blocksum128(float v, float* red4, int t) {
#pragma unroll
    for (int o = 16; o > 0; o >>= 1) v += __shfl_xor_sync(0xffffffffu, v, o);
    if ((t & 31) == 0) red4[t >> 5] = v;
    __syncthreads();
    float s = red4[0] + red4[1] + red4[2] + red4[3];
    __syncthreads();
    return s;
}

// ------------------------------- router -------------------------------------
__global__ void router_kernel(const float* __restrict__ x,
                              const float* __restrict__ gw,
                              const float* __restrict__ gb,
                              float* __restrict__ logits,
                              float* __restrict__ rw)
{
    int warp = (blockIdx.x * blockDim.x + threadIdx.x) >> 5;
    int lane = threadIdx.x & 31;
    if (warp >= N_) return;
    const float* xr = x + (size_t)warp * D_;
    float acc[E_];
#pragma unroll
    for (int e = 0; e < E_; e++) acc[e] = 0.f;
    for (int i = lane; i < D_; i += 32) {
        float xv = xr[i];
        const float* g = gw + i * E_;
#pragma unroll
        for (int e = 0; e < E_; e++) acc[e] += xv * g[e];
    }
#pragma unroll
    for (int e = 0; e < E_; e++) {
#pragma unroll
        for (int o = 16; o > 0; o >>= 1)
            acc[e] += __shfl_down_sync(0xffffffffu, acc[e], o);
    }
    if (lane == 0) {
        float lg[E_];
#pragma unroll
        for (int e = 0; e < E_; e++) {
            lg[e] = acc[e] + gb[e];
            logits[warp * E_ + e] = lg[e];
        }
        int i1 = 0;
#pragma unroll
        for (int e = 1; e < E_; e++) if (lg[e] > lg[i1]) i1 = e;
        int i2 = -1;
#pragma unroll
        for (int e = 0; e < E_; e++) {
            if (e == i1) continue;
            if (i2 < 0 || lg[e] > lg[i2]) i2 = e;
        }
#pragma unroll
        for (int e = 0; e < E_; e++) {
            float r = 0.f;
            if (e == i1 || e == i2) {
                float mem = lg[e] > 0.f ? lg[e] : 0.f;
#pragma unroll
                for (int lvl = 0; lvl < 4; lvl++) {
                    float thr = 4.0f / (float)(1 << lvl);
                    if (mem >= thr) { r += thr; mem -= thr; }
                }
            }
            rw[warp * E_ + e] = r;
        }
    }
}

// -------------------------- build gather lists -------------------------------
__global__ void build_lists_kernel(const float* __restrict__ rw)
{
    int n = blockIdx.x * blockDim.x + threadIdx.x;
    if (n >= N_) return;
    int b = n >> 10;
#pragma unroll
    for (int e = 0; e < E_; e++) {
        if (rw[n * E_ + e] != 0.f) {
            int seg = e * B_ + b;
            int i = atomicAdd(&g_cnt[seg], 1);
            g_idx[seg * S_ + i] = n;
            g_pos[n * E_ + e] = i;
        }
    }
}

// ----------------------------- conversions -----------------------------------
// One launch converts x + all weights + packs K/V biases.
#define U0_ ((long long)N_ * D_ / 8)        // 262144
#define UW_ ((long long)E_ * DD_ / 8)       // 262144
#define UF_ ((long long)E_ * D_ * F_ / 8)   // 1048576
#define UB_ ((long long)E_ * 2 * D_ / 8)    // 1024
#define UTOT_ (U0_ + 4 * UW_ + 2 * UF_ + UB_)

__global__ void convall_kernel(const float* __restrict__ x,  const float* __restrict__ wq,
                               const float* __restrict__ wk, const float* __restrict__ wv,
                               const float* __restrict__ wo, const float* __restrict__ w1,
                               const float* __restrict__ w2,
                               const float* __restrict__ bk, const float* __restrict__ bv)
{
    long long u = (long long)blockIdx.x * blockDim.x + threadIdx.x;
    if (u >= U0_ + 4 * UW_ + 2 * UF_) {     // bias pack segment (float copy)
        long long so = u - (U0_ + 4 * UW_ + 2 * UF_);
        long long gi = so * 8;
        int e = (int)(gi >> 10);
        int r = (int)(gi & 1023);
        int w = r >> 9;
        int d = r & 511;
        const float* s = (w == 0 ? bk : bv) + e * D_ + d;
        *(float4*)(g_bkv + gi)     = *(const float4*)(s);
        *(float4*)(g_bkv + gi + 4) = *(const float4*)(s + 4);
        return;
    }
    const float* src; __half* dst;
    long long so, dofs;
    if (u < U0_)                  { src = x;  dst = g_xh;  so = u;       dofs = so; }
    else if (u < U0_ + UW_)       { src = wq; dst = g_wqh; so = u - U0_; dofs = so; }
    else if (u < U0_ + 2 * UW_)   { so = u - U0_ - UW_;
                                    long long gi = so * 8;
                                    long long e = gi / DD_, r = gi - e * DD_;
                                    src = wk; dst = g_wkvh;
                                    dofs = (e * 2 * DD_ + r) >> 3; }
    else if (u < U0_ + 3 * UW_)   { so = u - U0_ - 2 * UW_;
                                    long long gi = so * 8;
                                    long long e = gi / DD_, r = gi - e * DD_;
                                    src = wv; dst = g_wkvh;
                                    dofs = (e * 2 * DD_ + DD_ + r) >> 3; }
    else if (u < U0_ + 4 * UW_)   { src = wo; dst = g_woh; so = u - U0_ - 3 * UW_; dofs = so; }
    else if (u < U0_ + 4 * UW_ + UF_) { src = w1; dst = g_w1h; so = u - U0_ - 4 * UW_; dofs = so; }
    else                          { src = w2; dst = g_w2h; so = u - U0_ - 4 * UW_ - UF_; dofs = so; }
    long long si = so * 8, di = dofs * 8;
    float4 a = *(const float4*)(src + si);
    float4 b = *(const float4*)(src + si + 4);
    *(__half2*)(dst + di)     = __floats2half2_rn(a.x, a.y);
    *(__half2*)(dst + di + 2) = __floats2half2_rn(a.z, a.w);
    *(__half2*)(dst + di + 4) = __floats2half2_rn(b.x, b.y);
    *(__half2*)(dst + di + 6) = __floats2half2_rn(b.z, b.w);
}

// --------------------------- fp16 tensor GEMM --------------------------------
// C = A[.,K] @ B[K][N] + bias (relu). A fp16 K-major (ldmatrix.x4); B fp16
// untransposed [K][N] (ldmatrix.x2.trans). BM=BN=128, BK=64, 256 thr,
// 8 warps of 64x32. 2-stage double buffer, ONE barrier per 64-K chunk.
#define HAP2 72
#define BSTR 136
#define ASTG (128 * HAP2)
#define BSTG (64 * BSTR)
#define HGEMM_SMEM (2 * (ASTG + BSTG) * 2)

template <bool RELU>
__global__ __launch_bounds__(256, 2) void hgemm(
    const __half* __restrict__ A, const __half* __restrict__ Bp,
    __half* __restrict__ Ch, float* __restrict__ Cf,
    const float* __restrict__ bias,
    int K, int lda, int ldb, int ldc,
    int div1,
    long long sA0, long long sA1,
    long long sB0, long long sB1,
    long long sC0, long long sC1,
    long long sb0, long long sb1,
    const int* __restrict__ mlim, const int* __restrict__ gidx)
{
    const int z  = blockIdx.z;
    const int bm = blockIdx.y * 128;
    if (mlim && bm >= mlim[z]) return;
    const int z0 = z / div1, z1 = z - z0 * div1;
    A  += z0 * sA0 + z1 * sA1;
    Bp += z0 * sB0 + z1 * sB1;
    const long long coff = z0 * sC0 + z1 * sC1;
    const float* biasp = bias + z0 * sb0 + z1 * sb1;

    extern __shared__ __half hsm[];
    __half* As = hsm;                    // [2][ASTG]
    __half* Bs = hsm + 2 * ASTG;         // [2][BSTG]

    const int tid  = threadIdx.x;
    const int lane = tid & 31;
    const int wid  = tid >> 5;
    const int warpM = (wid >> 2) * 64;
    const int warpN = (wid & 3) * 32;
    const int bn = blockIdx.x * 128;

    // A staging: 4 x 16B per thread (row tid>>1, cols (tid&1)*32 + j*8)
    const int srow = tid >> 1;
    const int acb  = (tid & 1) * 32;
    long long arow = bm + srow;
    if (gidx) arow = gidx[(long long)z * S_ + arow];
    const __half* gA = A + arow * lda + acb;
    uint32_t sA = (uint32_t)__cvta_generic_to_shared(As + srow * HAP2 + acb);

    // B staging: 4 x 16B per thread (rows tid>>4 + j*16, cols (tid&15)*8)
    const int brow0 = tid >> 4;
    const int bcol  = (tid & 15) * 8;
    const __half* gB = Bp + (long long)brow0 * ldb + bn + bcol;
    uint32_t sB = (uint32_t)__cvta_generic_to_shared(Bs + brow0 * BSTR + bcol);

    const uint32_t stgA = ASTG * 2;      // stage bytes
    const uint32_t stgB = BSTG * 2;
    const long long ldb16 = 16LL * ldb;

    float acc[4][4][4];
#pragma unroll
    for (int i = 0; i < 4; i++)
#pragma unroll
        for (int j = 0; j < 4; j++)
#pragma unroll
            for (int q = 0; q < 4; q++) acc[i][j][q] = 0.f;

    // prologue: chunk 0 -> stage 0
#pragma unroll
    for (int j = 0; j < 4; j++) cp_async16(sA + j * 16, gA + j * 8);
#pragma unroll
    for (int j = 0; j < 4; j++) cp_async16(sB + j * (16 * BSTR * 2), gB + j * ldb16);
    cp_commit();

    const int qq2 = (lane & 3) * 2;
    const int aRow = warpM + (lane & 15);
    const int aCol = (lane >> 4) << 3;
    const int nch = K >> 6;

    for (int it = 0; it < nch; it++) {
        const int s = it & 1;
        cp_wait0();
        __syncthreads();

        if (it + 1 < nch) {
            const int sp = s ^ 1;
            const long long koff = (long long)(it + 1) * 64;
            const __half* gA2 = gA + koff;
            const __half* gB2 = gB + koff * ldb;
#pragma unroll
            for (int j = 0; j < 4; j++) cp_async16(sA + sp * stgA + j * 16, gA2 + j * 8);
#pragma unroll
            for (int j = 0; j < 4; j++) cp_async16(sB + sp * stgB + j * (16 * BSTR * 2),
                                                   gB2 + j * ldb16);
            cp_commit();
        }

        const __half* As0 = As + s * ASTG;
        const __half* Bs0 = Bs + s * BSTG;
        uint32_t aBase = (uint32_t)__cvta_generic_to_shared(As0 + aRow * HAP2 + aCol);

#pragma unroll
        for (int ks = 0; ks < 4; ks++) {
            const int kb = ks * 16;
            unsigned af[4][4], bf[4][2];
#pragma unroll
            for (int mi = 0; mi < 4; mi++) {
                asm volatile(
                    "ldmatrix.sync.aligned.m8n8.x4.shared.b16 {%0,%1,%2,%3}, [%4];\n"
                    : "=r"(af[mi][0]), "=r"(af[mi][1]), "=r"(af[mi][2]), "=r"(af[mi][3])
                    : "r"(aBase + (mi * 16 * HAP2 + kb) * 2));
            }
            uint32_t bbase = (uint32_t)__cvta_generic_to_shared(
                Bs0 + (kb + (lane & 15)) * BSTR + warpN);
#pragma unroll
            for (int ni = 0; ni < 4; ni++) {
                asm volatile(
                    "ldmatrix.sync.aligned.m8n8.x2.trans.shared.b16 {%0,%1}, [%2];\n"
                    : "=r"(bf[ni][0]), "=r"(bf[ni][1]) : "r"(bbase + ni * 16));
            }
#pragma unroll
            for (int mi = 0; mi < 4; mi++)
#pragma unroll
                for (int ni = 0; ni < 4; ni++)
                    mma_f16(acc[mi][ni], af[mi][0], af[mi][1], af[mi][2], af[mi][3],
                            bf[ni][0], bf[ni][1]);
        }
    }

    // epilogue
#pragma unroll
    for (int mi = 0; mi < 4; mi++) {
        long long row0 = bm + warpM + mi * 16 + (lane >> 2);
#pragma unroll
        for (int ni = 0; ni < 4; ni++) {
            int col = bn + warpN + ni * 8 + qq2;
            float b0 = biasp[col], b1 = biasp[col + 1];
            float v0 = acc[mi][ni][0] + b0;
            float v1 = acc[mi][ni][1] + b1;
            float v2 = acc[mi][ni][2] + b0;
            float v3 = acc[mi][ni][3] + b1;
            if (RELU) {
                v0 = fmaxf(v0, 0.f); v1 = fmaxf(v1, 0.f);
                v2 = fmaxf(v2, 0.f); v3 = fmaxf(v3, 0.f);
            }
            if (Ch) {
                *(__half2*)(Ch + coff + row0 * ldc + col)       = __floats2half2_rn(v0, v1);
                *(__half2*)(Ch + coff + (row0 + 8) * ldc + col) = __floats2half2_rn(v2, v3);
            }
            if (Cf) {
                *(float2*)(Cf + coff + row0 * ldc + col)       = make_float2(v0, v1);
                *(float2*)(Cf + coff + (row0 + 8) * ldc + col) = make_float2(v2, v3);
            }
        }
    }
}

// ------------------------- fused flash attention (fp16) ----------------------
#define BC_   64
#define FSTR  136
#define FLASH_SMEM ((128 * FSTR + 2 * BC_ * FSTR + 2 * BC_ * FSTR) * 2)

__global__ __launch_bounds__(256, 2) void flash_kernel(const __half* __restrict__ qh,
                                                       const __half* __restrict__ kvh,
                                                       const int* __restrict__ cnt,
                                                       __half* __restrict__ ogh)
{
    const int qt  = blockIdx.x;
    const int seg = blockIdx.y >> 2;
    const int h   = blockIdx.y & 3;
    if (qt * 128 >= cnt[seg]) return;
    const int e = seg >> 2;
    const int b = seg & 3;

    extern __shared__ __half fsm[];
    __half* Qs = fsm;
    __half* Ks = fsm + 128 * FSTR;
    __half* Vs = Ks + 2 * BC_ * FSTR;

    const int tid  = threadIdx.x;
    const int lane = tid & 31;
    const int wid  = tid >> 5;
    const float scale = 0.08838834764831845f;

    const __half* qbase = qh + (long long)seg * SD_ + (long long)(qt * 128) * D_ + h * DH_;
    const __half* kbase = kvh + (long long)e * 2 * ND_ + (long long)(b * S_) * D_ + h * DH_;
    const __half* vbase = kbase + ND_;

    {
        int r = tid >> 1, c0 = (tid & 1) * 64;
        const __half* g = qbase + (long long)r * D_ + c0;
        uint32_t s = (uint32_t)__cvta_generic_to_shared(Qs + r * FSTR + c0);
#pragma unroll
        for (int j = 0; j < 8; j++) cp_async16(s + j * 16, g + j * 8);
    }
    {
        int r = tid >> 2, c0 = (tid & 3) * 32;
        const __half* gk = kbase + (long long)r * D_ + c0;
        const __half* gv = vbase + (long long)r * D_ + c0;
        uint32_t sk = (uint32_t)__cvta_generic_to_shared(Ks + r * FSTR + c0);
        uint32_t sv = (uint32_t)__cvta_generic_to_shared(Vs + r * FSTR + c0);
#pragma unroll
        for (int j = 0; j < 4; j++) {
            cp_async16(sk + j * 16, gk + j * 8);
            cp_async16(sv + j * 16, gv + j * 8);
        }
    }
    cp_commit();

    const int r0  = lane >> 2;
    const int qq2 = (lane & 3) * 2;
    const int wrow = wid * 16;

    float oacc[16][4];
#pragma unroll
    for (int i = 0; i < 16; i++)
#pragma unroll
        for (int j = 0; j < 4; j++) oacc[i][j] = 0.f;
    float m0 = -1e30f, m1 = -1e30f, l0 = 0.f, l1 = 0.f;

    const int qRow = wrow + (lane & 15);
    const int qCol = (lane >> 4) << 3;
    const int kRow = lane & 7;
    const int kCol = ((lane >> 3) & 1) << 3;

    for (int t = 0; t < 16; t++) {
        const int st = t & 1;
        cp_wait0();
        __syncthreads();

        if (t < 15) {
            int r = tid >> 2, c0 = (tid & 3) * 32;
            int st2 = st ^ 1;
            const __half* gk = kbase + (long long)((t + 1) * BC_ + r) * D_ + c0;
            const __half* gv = vbase + (long long)((t + 1) * BC_ + r) * D_ + c0;
            uint32_t sk = (uint32_t)__cvta_generic_to_shared(Ks + st2 * BC_ * FSTR + r * FSTR + c0);
            uint32_t sv = (uint32_t)__cvta_generic_to_shared(Vs + st2 * BC_ * FSTR + r * FSTR + c0);
#pragma unroll
            for (int j = 0; j < 4; j++) {
                cp_async16(sk + j * 16, gk + j * 8);
                cp_async16(sv + j * 16, gv + j * 8);
            }
            cp_commit();
        }

        float sacc[8][4];
#pragma unroll
        for (int i = 0; i < 8; i++)
#pragma unroll
            for (int j = 0; j < 4; j++) sacc[i][j] = 0.f;

        const __half* Kt = Ks + st * BC_ * FSTR;
        uint32_t qaddr = (uint32_t)__cvta_generic_to_shared(Qs + qRow * FSTR + qCol);
        uint32_t kaddr = (uint32_t)__cvta_generic_to_shared(Kt + kRow * FSTR + kCol);
#pragma unroll
        for (int ks = 0; ks < 8; ks++) {
            const int kbB = ks * 16 * 2;
            unsigned a0, a1, a2, a3;
            asm volatile(
                "ldmatrix.sync.aligned.m8n8.x4.shared.b16 {%0,%1,%2,%3}, [%4];\n"
                : "=r"(a0), "=r"(a1), "=r"(a2), "=r"(a3)
                : "r"(qaddr + kbB));
#pragma unroll
            for (int ni = 0; ni < 8; ni++) {
                unsigned b0, b1;
                asm volatile(
                    "ldmatrix.sync.aligned.m8n8.x2.shared.b16 {%0,%1}, [%2];\n"
                    : "=r"(b0), "=r"(b1)
                    : "r"(kaddr + kbB + ni * 8 * FSTR * 2));
                mma_f16(sacc[ni], a0, a1, a2, a3, b0, b1);
            }
        }

        float rmax0 = -1e30f, rmax1 = -1e30f;
#pragma unroll
        for (int ni = 0; ni < 8; ni++) {
            sacc[ni][0] *= scale; sacc[ni][1] *= scale;
            sacc[ni][2] *= scale; sacc[ni][3] *= scale;
            rmax0 = fmaxf(rmax0, fmaxf(sacc[ni][0], sacc[ni][1]));
            rmax1 = fmaxf(rmax1, fmaxf(sacc[ni][2], sacc[ni][3]));
        }
        rmax0 = fmaxf(rmax0, __shfl_xor_sync(0xffffffffu, rmax0, 1));
        rmax0 = fmaxf(rmax0, __shfl_xor_sync(0xffffffffu, rmax0, 2));
        rmax1 = fmaxf(rmax1, __shfl_xor_sync(0xffffffffu, rmax1, 1));
        rmax1 = fmaxf(rmax1, __shfl_xor_sync(0xffffffffu, rmax1, 2));
        float mn0 = fmaxf(m0, rmax0), mn1 = fmaxf(m1, rmax1);
        float c0 = __expf(m0 - mn0), c1 = __expf(m1 - mn1);
        m0 = mn0; m1 = mn1;
        float rs0 = 0.f, rs1 = 0.f;
#pragma unroll
        for (int ni = 0; ni < 8; ni++) {
            sacc[ni][0] = __expf(sacc[ni][0] - m0);
            sacc[ni][1] = __expf(sacc[ni][1] - m0);
            sacc[ni][2] = __expf(sacc[ni][2] - m1);
            sacc[ni][3] = __expf(sacc[ni][3] - m1);
            rs0 += sacc[ni][0] + sacc[ni][1];
            rs1 += sacc[ni][2] + sacc[ni][3];
        }
        rs0 += __shfl_xor_sync(0xffffffffu, rs0, 1);
        rs0 += __shfl_xor_sync(0xffffffffu, rs0, 2);
        rs1 += __shfl_xor_sync(0xffffffffu, rs1, 1);
        rs1 += __shfl_xor_sync(0xffffffffu, rs1, 2);
        l0 = l0 * c0 + rs0;
        l1 = l1 * c1 + rs1;
#pragma unroll
        for (int ni = 0; ni < 16; ni++) {
            oacc[ni][0] *= c0; oacc[ni][1] *= c0;
            oacc[ni][2] *= c1; oacc[ni][3] *= c1;
        }

        const __half* Vt = Vs + st * BC_ * FSTR;
#pragma unroll
        for (int ks = 0; ks < 4; ks++) {
            unsigned a0 = h2pack(sacc[2 * ks][0],     sacc[2 * ks][1]);
            unsigned a1 = h2pack(sacc[2 * ks][2],     sacc[2 * ks][3]);
            unsigned a2 = h2pack(sacc[2 * ks + 1][0], sacc[2 * ks + 1][1]);
            unsigned a3 = h2pack(sacc[2 * ks + 1][2], sacc[2 * ks + 1][3]);
            uint32_t vrow = (uint32_t)__cvta_generic_to_shared(
                Vt + (16 * ks + (lane & 15)) * FSTR);
#pragma unroll
            for (int ni = 0; ni < 16; ni++) {
                unsigned b0, b1;
                asm volatile(
                    "ldmatrix.sync.aligned.m8n8.x2.trans.shared.b16 {%0,%1}, [%2];\n"
                    : "=r"(b0), "=r"(b1) : "r"(vrow + ni * 16));
                mma_f16(oacc[ni], a0, a1, a2, a3, b0, b1);
            }
        }
    }

    float inv0 = 1.f / l0, inv1 = 1.f / l1;
    long long row0 = (long long)(qt * 128 + wrow + r0);
    __half* ob = ogh + (long long)seg * SD_ + row0 * D_ + h * DH_;
#pragma unroll
    for (int ni = 0; ni < 16; ni++) {
        int col = ni * 8 + qq2;
        *(__half2*)(ob + col)            = __floats2half2_rn(oacc[ni][0] * inv0, oacc[ni][1] * inv0);
        *(__half2*)(ob + 8LL * D_ + col) = __floats2half2_rn(oacc[ni][2] * inv1, oacc[ni][3] * inv1);
    }
}

// --------------------------- LayerNorm kernels ------------------------------
__global__ void ln1g_kernel(const float* __restrict__ x, const float* __restrict__ t1,
                            const int* __restrict__ idx, const int* __restrict__ cnt,
                            const float* __restrict__ s_all, const float* __restrict__ b_all,
                            float* __restrict__ hg, __half* __restrict__ hgh)
{
    int i   = blockIdx.x;
    int seg = blockIdx.y;
    if (i >= cnt[seg]) return;
    int e = seg >> 2;
    int token = idx[seg * S_ + i];
    const float* a    = x  + (size_t)token * D_;
    const float* bsrc = t1 + ((size_t)seg * S_ + i) * D_;
    const float* s    = s_all + (size_t)e * D_;
    const float* bb   = b_all + (size_t)e * D_;
    float*  outf = hg  + ((size_t)seg * S_ + i) * D_;
    __half* outh = hgh + ((size_t)seg * S_ + i) * D_;
    int t = threadIdx.x;
    __shared__ float red4[4];
    float v[4];
#pragma unroll
    for (int q = 0; q < 4; q++) {
        int d = t + q * 128;
        v[q] = a[d] + bsrc[d];
    }
    float mu = blocksum128(v[0] + v[1] + v[2] + v[3], red4, t) * (1.f / D_);
    float sq = 0.f;
#pragma unroll
    for (int q = 0; q < 4; q++) { float d2 = v[q] - mu; sq += d2 * d2; }
    float inv = rsqrtf(blocksum128(sq, red4, t) * (1.f / D_) + LN_EPS);
#pragma unroll
    for (int q = 0; q < 4; q++) {
        int d = t + q * 128;
        float y = (v[q] - mu) * inv * s[d] + bb[d];
        outf[d] = y;
        outh[d] = __float2half_rn(y);
    }
}

__global__ void ln2_scatter_kernel(const float* __restrict__ hg, const float* __restrict__ f2g,
                                   const float* __restrict__ s_all, const float* __restrict__ b_all,
                                   const float* __restrict__ rw, const int* __restrict__ pos,
                                   float* __restrict__ finalOut)
{
    int n = blockIdx.x;
    int t = threadIdx.x;
    int b = n >> 10;
    __shared__ float red4[4];
    float outv[4] = {0.f, 0.f, 0.f, 0.f};
    for (int e = 0; e < E_; e++) {
        float w = rw[n * E_ + e];
        if (w == 0.f) continue;
        int seg = e * B_ + b;
        int p = pos[n * E_ + e];
        const float* hp = hg  + ((size_t)seg * S_ + p) * D_;
        const float* fp = f2g + ((size_t)seg * S_ + p) * D_;
        const float* s  = s_all + (size_t)e * D_;
        const float* bb = b_all + (size_t)e * D_;
        float v[4];
#pragma unroll
        for (int q = 0; q < 4; q++) {
            int d = t + q * 128;
            v[q] = hp[d] + fp[d];
        }
        float mu = blocksum128(v[0] + v[1] + v[2] + v[3], red4, t) * (1.f / D_);
        float sq = 0.f;
#pragma unroll
        for (int q = 0; q < 4; q++) { float d2 = v[q] - mu; sq += d2 * d2; }
        float inv = rsqrtf(blocksum128(sq, red4, t) * (1.f / D_) + LN_EPS);
#pragma unroll
        for (int q = 0; q < 4; q++) {
            int d = t + q * 128;
            outv[q] += w * ((v[q] - mu) * inv * s[d] + bb[d]);
        }
    }
#pragma unroll
    for (int q = 0; q < 4; q++)
        finalOut[(size_t)n * D_ + t + q * 128] = outv[q];
}

// ------------------------------ host glue -----------------------------------
extern "C" void kernel_launch(void* const* d_in, const int* in_sizes, int n_in,
                              void* d_out, int out_size)
{
    const float* x      = (const float*)d_in[0];
    const float* gate_w = (const float*)d_in[1];
    const float* gate_b = (const float*)d_in[2];
    const float* ln1_s  = (const float*)d_in[3];
    const float* ln1_b  = (const float*)d_in[4];
    const float* ln2_s  = (const float*)d_in[5];
    const float* ln2_b  = (const float*)d_in[6];
    const float* wq     = (const float*)d_in[7];
    const float* wk     = (const float*)d_in[8];
    const float* wv     = (const float*)d_in[9];
    const float* wo     = (const float*)d_in[10];
    const float* bq     = (const float*)d_in[11];
    const float* bk     = (const float*)d_in[12];
    const float* bv     = (const float*)d_in[13];
    const float* bo     = (const float*)d_in[14];
    const float* w1     = (const float*)d_in[15];
    const float* b1     = (const float*)d_in[16];
    const float* w2     = (const float*)d_in[17];
    const float* b2     = (const float*)d_in[18];

    float* out_final  = (float*)d_out;
    float* out_logits = out_final + (size_t)N_ * D_;

    float *rw, *t1, *hg, *f2, *bkv;
    int *cnt, *idx, *pos;
    __half *xh, *wqh, *wkvh, *woh, *w1h, *w2h, *kvh, *qh, *ogh, *hgh, *f1h;
    cudaGetSymbolAddress((void**)&rw,   g_rw);
    cudaGetSymbolAddress((void**)&cnt,  g_cnt);
    cudaGetSymbolAddress((void**)&idx,  g_idx);
    cudaGetSymbolAddress((void**)&pos,  g_pos);
    cudaGetSymbolAddress((void**)&bkv,  g_bkv);
    cudaGetSymbolAddress((void**)&xh,   g_xh);
    cudaGetSymbolAddress((void**)&wqh,  g_wqh);
    cudaGetSymbolAddress((void**)&wkvh, g_wkvh);
    cudaGetSymbolAddress((void**)&woh,  g_woh);
    cudaGetSymbolAddress((void**)&w1h,  g_w1h);
    cudaGetSymbolAddress((void**)&w2h,  g_w2h);
    cudaGetSymbolAddress((void**)&kvh,  g_kvh);
    cudaGetSymbolAddress((void**)&qh,   g_qh);
    cudaGetSymbolAddress((void**)&ogh,  g_ogh);
    cudaGetSymbolAddress((void**)&hgh,  g_hgh);
    cudaGetSymbolAddress((void**)&f1h,  g_f1h);
    cudaGetSymbolAddress((void**)&t1,   g_t1);
    cudaGetSymbolAddress((void**)&hg,   g_hg);
    cudaGetSymbolAddress((void**)&f2,   g_f2);

    static cudaStream_t s_aux = nullptr;
    static cudaEvent_t evFork = nullptr, evJoin = nullptr;
    if (!s_aux) {
        cudaStreamCreateWithFlags(&s_aux, cudaStreamNonBlocking);
        cudaEventCreateWithFlags(&evFork, cudaEventDisableTiming);
        cudaEventCreateWithFlags(&evJoin, cudaEventDisableTiming);
    }

    cudaFuncSetAttribute(flash_kernel,
                         cudaFuncAttributeMaxDynamicSharedMemorySize, FLASH_SMEM);
    cudaFuncSetAttribute(hgemm<false>,
                         cudaFuncAttributeMaxDynamicSharedMemorySize, HGEMM_SMEM);
    cudaFuncSetAttribute(hgemm<true>,
                         cudaFuncAttributeMaxDynamicSharedMemorySize, HGEMM_SMEM);

    // ---- fork: router + gather lists on aux stream ----
    cudaEventRecord(evFork, 0);
    cudaStreamWaitEvent(s_aux, evFork, 0);
    cudaMemsetAsync(cnt, 0, SEGS * sizeof(int), s_aux);
    cudaMemsetAsync(idx, 0, SEGS * S_ * sizeof(int), s_aux);
    router_kernel<<<N_ / 8, 256, 0, s_aux>>>(x, gate_w, gate_b, out_logits, rw);
    build_lists_kernel<<<N_ / 256, 256, 0, s_aux>>>(rw);
    cudaEventRecord(evJoin, s_aux);

    // ---- main stream: conversions + dense K/V GEMM (independent of router) ----
    convall_kernel<<<(int)(UTOT_ / 256), 256>>>(x, wq, wk, wv, wo, w1, w2, bk, bv);

    // K+V projections merged (dense): z = e*2 + {k,v}
    {
        dim3 grid(D_ / 128, N_ / 128, E_ * 2);
        hgemm<false><<<grid, 256, HGEMM_SMEM>>>(
            xh, wkvh, kvh, nullptr, bkv,
            D_, D_, D_, D_,
            2,
            0, 0,
            2LL * DD_, DD_,
            2 * ND_, ND_,
            2LL * D_, D_,
            nullptr, nullptr);
    }

    // ---- join: everything below needs the gather lists ----
    cudaStreamWaitEvent(0, evJoin, 0);

    // Q projection (gathered): z = seg
    {
        dim3 grid(D_ / 128, S_ / 128, SEGS);
        hgemm<false><<<grid, 256, HGEMM_SMEM>>>(
            xh, wqh, qh, nullptr, bq,
            D_, D_, D_, D_,
            B_,
            0, 0,
            DD_, 0,
            (long long)B_ * SD_, SD_,
            D_, 0,
            cnt, idx);
    }

    // fused attention
    {
        dim3 grid(S_ / 128, SEGS * H_);
        flash_kernel<<<grid, 256, FLASH_SMEM>>>(qh, kvh, cnt, ogh);
    }

    // O projection -> t1 (fp32): z = seg
    {
        dim3 grid(D_ / 128, S_ / 128, SEGS);
        hgemm<false><<<grid, 256, HGEMM_SMEM>>>(
            ogh, woh, nullptr, t1, bo,
            D_, D_, D_, D_,
            B_,
            (long long)B_ * SD_, SD_,
            DD_, 0,
            (long long)B_ * SD_, SD_,
            D_, 0,
            cnt, nullptr);
    }

    // LN1 -> hg (fp32) + hgh (fp16)
    {
        dim3 grid(S_, SEGS);
        ln1g_kernel<<<grid, 128>>>(x, t1, idx, cnt, ln1_s, ln1_b, hg, hgh);
    }

    // FFN1 -> f1h (relu): z = seg
    {
        dim3 grid(F_ / 128, S_ / 128, SEGS);
        hgemm<true><<<grid, 256, HGEMM_SMEM>>>(
            hgh, w1h, f1h, nullptr, b1,
            D_, D_, F_, F_,
            B_,
            (long long)B_ * SD_, SD_,
            (long long)D_ * F_, 0,
            (long long)B_ * SF_, SF_,
            F_, 0,
            cnt, nullptr);
    }

    // FFN2 -> f2 (fp32): z = seg
    {
        dim3 grid(D_ / 128, S_ / 128, SEGS);
        hgemm<false><<<grid, 256, HGEMM_SMEM>>>(
            f1h, w2h, nullptr, f2, b2,
            F_, F_, D_, D_,
            B_,
            (long long)B_ * SF_, SF_,
            (long long)F_ * D_, 0,
            (long long)B_ * SD_, SD_,
            D_, 0,
            cnt, nullptr);
    }

    // final = sum_e rw * LN2(hg + f2)
    ln2_scatter_kernel<<<N_, 128>>>(hg, f2, ln2_s, ln2_b, rw, pos, out_final);
}

// round 13
// speedup vs baseline: 1.0858x; 1.0858x over previous
#include <cuda_runtime.h>
#include <cuda_fp16.h>
#include <cstdint>

// ---------------------------------------------------------------------------
// SEMMBlock: spiking-router MoE transformer block.
// B=4 S=1024 D=512 E=8 F=2048 H=4 dh=128.
// Round 13: round-12 with the FFN2 ldb bug fixed (ldb = D_, matching w2's
// [F][D] layout). hgemm = round-10 proven BK=32 3-stage pipeline; fork/join
// for router; one-shot conversion kernel.
// ---------------------------------------------------------------------------

#define B_  4
#define S_  1024
#define D_  512
#define E_  8
#define F_  2048
#define H_  4
#define DH_ 128
#define N_  (B_ * S_)
#define SEGS (E_ * B_)
#define LN_EPS 1e-5f

#define DD_  (D_ * D_)
#define ND_  ((long long)N_ * D_)
#define SD_  ((long long)S_ * D_)
#define SF_  ((long long)S_ * F_)

// ------------------------- scratch (device globals) ------------------------
__device__ float  g_rw[N_ * E_];
__device__ int    g_cnt[SEGS];
__device__ int    g_idx[SEGS * S_];
__device__ int    g_pos[N_ * E_];
__device__ float  g_bkv[E_ * 2 * D_];
__device__ __half g_xh[N_ * D_];
__device__ __half g_wqh[E_ * DD_];             // [e][K][N] fp16 (untransposed)
__device__ __half g_wkvh[(size_t)E_ * 2 * DD_];// [e][{k,v}][K][N]
__device__ __half g_woh[E_ * DD_];
__device__ __half g_w1h[(size_t)E_ * D_ * F_];
__device__ __half g_w2h[(size_t)E_ * F_ * D_];
__device__ __half g_kvh[(size_t)E_ * 2 * N_ * D_];
__device__ __half g_qh[(size_t)SEGS * S_ * D_];
__device__ __half g_ogh[(size_t)SEGS * S_ * D_];
__device__ __half g_hgh[(size_t)SEGS * S_ * D_];
__device__ __half g_f1h[(size_t)SEGS * S_ * F_];
__device__ float  g_t1[(size_t)SEGS * S_ * D_];
__device__ float  g_hg[(size_t)SEGS * S_ * D_];
__device__ float  g_f2[(size_t)SEGS * S_ * D_];

// ------------------------------ helpers -------------------------------------
__device__ __forceinline__ void cp_async16(uint32_t smem, const void* gptr) {
    asm volatile("cp.async.cg.shared.global [%0], [%1], 16;\n" :: "r"(smem), "l"(gptr));
}
__device__ __forceinline__ void cp_commit() {
    asm volatile("cp.async.commit_group;\n");
}
__device__ __forceinline__ void cp_wait0() {
    asm volatile("cp.async.wait_group 0;\n");
}
__device__ __forceinline__ void cp_wait1() {
    asm volatile("cp.async.wait_group 1;\n");
}
__device__ __forceinline__ void mma_f16(float* c, unsigned a0, unsigned a1,
                                        unsigned a2, unsigned a3,
                                        unsigned b0, unsigned b1) {
    asm volatile(
        "mma.sync.aligned.m16n8k16.row.col.f32.f16.f16.f32 "
        "{%0,%1,%2,%3}, {%4,%5,%6,%7}, {%8,%9}, {%0,%1,%2,%3};\n"
        : "+f"(c[0]), "+f"(c[1]), "+f"(c[2]), "+f"(c[3])
        : "r"(a0), "r"(a1), "r"(a2), "r"(a3), "r"(b0), "r"(b1));
}
__device__ __forceinline__ unsigned h2pack(float x, float y) {
    __half2 h = __floats2half2_rn(x, y);
    return *(unsigned*)&h;
}
__device__ __forceinline__ float blocksum128(float v, float* red4, int t) {
#pragma unroll
    for (int o = 16; o > 0; o >>= 1) v += __shfl_xor_sync(0xffffffffu, v, o);
    if ((t & 31) == 0) red4[t >> 5] = v;
    __syncthreads();
    float s = red4[0] + red4[1] + red4[2] + red4[3];
    __syncthreads();
    return s;
}

// ------------------------------- router -------------------------------------
__global__ void router_kernel(const float* __restrict__ x,
                              const float* __restrict__ gw,
                              const float* __restrict__ gb,
                              float* __restrict__ logits,
                              float* __restrict__ rw)
{
    int warp = (blockIdx.x * blockDim.x + threadIdx.x) >> 5;
    int lane = threadIdx.x & 31;
    if (warp >= N_) return;
    const float* xr = x + (size_t)warp * D_;
    float acc[E_];
#pragma unroll
    for (int e = 0; e < E_; e++) acc[e] = 0.f;
    for (int i = lane; i < D_; i += 32) {
        float xv = xr[i];
        const float* g = gw + i * E_;
#pragma unroll
        for (int e = 0; e < E_; e++) acc[e] += xv * g[e];
    }
#pragma unroll
    for (int e = 0; e < E_; e++) {
#pragma unroll
        for (int o = 16; o > 0; o >>= 1)
            acc[e] += __shfl_down_sync(0xffffffffu, acc[e], o);
    }
    if (lane == 0) {
        float lg[E_];
#pragma unroll
        for (int e = 0; e < E_; e++) {
            lg[e] = acc[e] + gb[e];
            logits[warp * E_ + e] = lg[e];
        }
        int i1 = 0;
#pragma unroll
        for (int e = 1; e < E_; e++) if (lg[e] > lg[i1]) i1 = e;
        int i2 = -1;
#pragma unroll
        for (int e = 0; e < E_; e++) {
            if (e == i1) continue;
            if (i2 < 0 || lg[e] > lg[i2]) i2 = e;
        }
#pragma unroll
        for (int e = 0; e < E_; e++) {
            float r = 0.f;
            if (e == i1 || e == i2) {
                float mem = lg[e] > 0.f ? lg[e] : 0.f;
#pragma unroll
                for (int lvl = 0; lvl < 4; lvl++) {
                    float thr = 4.0f / (float)(1 << lvl);
                    if (mem >= thr) { r += thr; mem -= thr; }
                }
            }
            rw[warp * E_ + e] = r;
        }
    }
}

// -------------------------- build gather lists -------------------------------
__global__ void build_lists_kernel(const float* __restrict__ rw)
{
    int n = blockIdx.x * blockDim.x + threadIdx.x;
    if (n >= N_) return;
    int b = n >> 10;
#pragma unroll
    for (int e = 0; e < E_; e++) {
        if (rw[n * E_ + e] != 0.f) {
            int seg = e * B_ + b;
            int i = atomicAdd(&g_cnt[seg], 1);
            g_idx[seg * S_ + i] = n;
            g_pos[n * E_ + e] = i;
        }
    }
}

// ----------------------------- conversions -----------------------------------
#define U0_ ((long long)N_ * D_ / 8)        // 262144
#define UW_ ((long long)E_ * DD_ / 8)       // 262144
#define UF_ ((long long)E_ * D_ * F_ / 8)   // 1048576
#define UB_ ((long long)E_ * 2 * D_ / 8)    // 1024
#define UTOT_ (U0_ + 4 * UW_ + 2 * UF_ + UB_)

__global__ void convall_kernel(const float* __restrict__ x,  const float* __restrict__ wq,
                               const float* __restrict__ wk, const float* __restrict__ wv,
                               const float* __restrict__ wo, const float* __restrict__ w1,
                               const float* __restrict__ w2,
                               const float* __restrict__ bk, const float* __restrict__ bv)
{
    long long u = (long long)blockIdx.x * blockDim.x + threadIdx.x;
    if (u >= U0_ + 4 * UW_ + 2 * UF_) {     // bias pack segment (float copy)
        long long so = u - (U0_ + 4 * UW_ + 2 * UF_);
        long long gi = so * 8;
        int e = (int)(gi >> 10);
        int r = (int)(gi & 1023);
        int w = r >> 9;
        int d = r & 511;
        const float* s = (w == 0 ? bk : bv) + e * D_ + d;
        *(float4*)(g_bkv + gi)     = *(const float4*)(s);
        *(float4*)(g_bkv + gi + 4) = *(const float4*)(s + 4);
        return;
    }
    const float* src; __half* dst;
    long long so, dofs;
    if (u < U0_)                  { src = x;  dst = g_xh;  so = u;       dofs = so; }
    else if (u < U0_ + UW_)       { src = wq; dst = g_wqh; so = u - U0_; dofs = so; }
    else if (u < U0_ + 2 * UW_)   { so = u - U0_ - UW_;
                                    long long gi = so * 8;
                                    long long e = gi / DD_, r = gi - e * DD_;
                                    src = wk; dst = g_wkvh;
                                    dofs = (e * 2 * DD_ + r) >> 3; }
    else if (u < U0_ + 3 * UW_)   { so = u - U0_ - 2 * UW_;
                                    long long gi = so * 8;
                                    long long e = gi / DD_, r = gi - e * DD_;
                                    src = wv; dst = g_wkvh;
                                    dofs = (e * 2 * DD_ + DD_ + r) >> 3; }
    else if (u < U0_ + 4 * UW_)   { src = wo; dst = g_woh; so = u - U0_ - 3 * UW_; dofs = so; }
    else if (u < U0_ + 4 * UW_ + UF_) { src = w1; dst = g_w1h; so = u - U0_ - 4 * UW_; dofs = so; }
    else                          { src = w2; dst = g_w2h; so = u - U0_ - 4 * UW_ - UF_; dofs = so; }
    long long si = so * 8, di = dofs * 8;
    float4 a = *(const float4*)(src + si);
    float4 b = *(const float4*)(src + si + 4);
    *(__half2*)(dst + di)     = __floats2half2_rn(a.x, a.y);
    *(__half2*)(dst + di + 2) = __floats2half2_rn(a.z, a.w);
    *(__half2*)(dst + di + 4) = __floats2half2_rn(b.x, b.y);
    *(__half2*)(dst + di + 6) = __floats2half2_rn(b.z, b.w);
}

// --------------------------- fp16 tensor GEMM --------------------------------
// C = A[.,K] @ B[K][N] + bias (relu). A fp16 K-major (ldmatrix.x4); B fp16
// untransposed [K][N] (ldmatrix.x2.trans). BM=BN=128, BK=32, 256 thr,
// 8 warps of 64x32. 3-stage cp.async pipeline, wait_group 1.
#define HAPAD 40
#define BSTR  136
#define HGEMM_SMEM (3 * (128 * HAPAD + 32 * BSTR) * 2)

template <bool RELU>
__global__ __launch_bounds__(256, 2) void hgemm(
    const __half* __restrict__ A, const __half* __restrict__ Bp,
    __half* __restrict__ Ch, float* __restrict__ Cf,
    const float* __restrict__ bias,
    int K, int lda, int ldb, int ldc,
    int div1,
    long long sA0, long long sA1,
    long long sB0, long long sB1,
    long long sC0, long long sC1,
    long long sb0, long long sb1,
    const int* __restrict__ mlim, const int* __restrict__ gidx)
{
    const int z  = blockIdx.z;
    const int bm = blockIdx.y * 128;
    if (mlim && bm >= mlim[z]) return;
    const int z0 = z / div1, z1 = z - z0 * div1;
    A  += z0 * sA0 + z1 * sA1;
    Bp += z0 * sB0 + z1 * sB1;
    const long long coff = z0 * sC0 + z1 * sC1;
    const float* biasp = bias + z0 * sb0 + z1 * sb1;

    extern __shared__ __half hsm[];
    __half* As = hsm;                        // [3][128*HAPAD]
    __half* Bs = hsm + 3 * 128 * HAPAD;      // [3][32*BSTR]

    const int tid  = threadIdx.x;
    const int lane = tid & 31;
    const int wid  = tid >> 5;
    const int warpM = (wid >> 2) * 64;
    const int warpN = (wid & 3) * 32;
    const int bn = blockIdx.x * 128;

    const int srow = tid >> 1;
    const int sch  = (tid & 1) * 16;
    long long arow = bm + srow;
    if (gidx) arow = gidx[(long long)z * S_ + arow];
    const __half* gA = A + arow * lda + sch;
    uint32_t sA = (uint32_t)__cvta_generic_to_shared(As + srow * HAPAD + sch);

    const int brow = tid >> 4;
    const int bc16 = (tid & 15) * 8;
    const __half* gB = Bp + (long long)brow * ldb + bn + bc16;
    uint32_t sB = (uint32_t)__cvta_generic_to_shared(Bs + brow * BSTR + bc16);

    const uint32_t stgA = 128 * HAPAD * 2;
    const uint32_t stgB = 32 * BSTR * 2;
    const long long ldb16 = 16LL * ldb;

    float acc[4][4][4];
#pragma unroll
    for (int i = 0; i < 4; i++)
#pragma unroll
        for (int j = 0; j < 4; j++)
#pragma unroll
            for (int q = 0; q < 4; q++) acc[i][j][q] = 0.f;

    cp_async16(sA,      gA);
    cp_async16(sA + 16, gA + 8);
    cp_async16(sB,                 gB);
    cp_async16(sB + 16 * BSTR * 2, gB + ldb16);
    cp_commit();
    cp_async16(sA + stgA,      gA + 32);
    cp_async16(sA + stgA + 16, gA + 40);
    cp_async16(sB + stgB,                 gB + 2 * ldb16);
    cp_async16(sB + stgB + 16 * BSTR * 2, gB + 3 * ldb16);
    cp_commit();

    const int qq2 = (lane & 3) * 2;
    const int aRow = warpM + (lane & 15);
    const int aCol = (lane >> 4) << 3;

    int it = 0;
    for (int k0 = 0; k0 < K; k0 += 32, it++) {
        const int st = it % 3;
        cp_wait1();
        __syncthreads();

        if (k0 + 64 < K) {
            const int sp = (it + 2) % 3;
            const __half* gA2 = gA + k0 + 64;
            const __half* gB2 = gB + (long long)(k0 + 64) * ldb;
            cp_async16(sA + sp * stgA,      gA2);
            cp_async16(sA + sp * stgA + 16, gA2 + 8);
            cp_async16(sB + sp * stgB,                 gB2);
            cp_async16(sB + sp * stgB + 16 * BSTR * 2, gB2 + ldb16);
        }
        cp_commit();

        const __half* As0 = As + st * 128 * HAPAD;
        const __half* Bs0 = Bs + st * 32 * BSTR;
        uint32_t aBase = (uint32_t)__cvta_generic_to_shared(As0 + aRow * HAPAD + aCol);

#pragma unroll
        for (int ks = 0; ks < 2; ks++) {
            const int kb = ks * 16;
            unsigned af[4][4], bf[4][2];
#pragma unroll
            for (int mi = 0; mi < 4; mi++) {
                asm volatile(
                    "ldmatrix.sync.aligned.m8n8.x4.shared.b16 {%0,%1,%2,%3}, [%4];\n"
                    : "=r"(af[mi][0]), "=r"(af[mi][1]), "=r"(af[mi][2]), "=r"(af[mi][3])
                    : "r"(aBase + (mi * 16 * HAPAD + kb) * 2));
            }
            uint32_t bbase = (uint32_t)__cvta_generic_to_shared(
                Bs0 + (kb + (lane & 15)) * BSTR + warpN);
#pragma unroll
            for (int ni = 0; ni < 4; ni++) {
                asm volatile(
                    "ldmatrix.sync.aligned.m8n8.x2.trans.shared.b16 {%0,%1}, [%2];\n"
                    : "=r"(bf[ni][0]), "=r"(bf[ni][1]) : "r"(bbase + ni * 16));
            }
#pragma unroll
            for (int mi = 0; mi < 4; mi++)
#pragma unroll
                for (int ni = 0; ni < 4; ni++)
                    mma_f16(acc[mi][ni], af[mi][0], af[mi][1], af[mi][2], af[mi][3],
                            bf[ni][0], bf[ni][1]);
        }
    }

    // epilogue
#pragma unroll
    for (int mi = 0; mi < 4; mi++) {
        long long row0 = bm + warpM + mi * 16 + (lane >> 2);
#pragma unroll
        for (int ni = 0; ni < 4; ni++) {
            int col = bn + warpN + ni * 8 + qq2;
            float b0 = biasp[col], b1 = biasp[col + 1];
            float v0 = acc[mi][ni][0] + b0;
            float v1 = acc[mi][ni][1] + b1;
            float v2 = acc[mi][ni][2] + b0;
            float v3 = acc[mi][ni][3] + b1;
            if (RELU) {
                v0 = fmaxf(v0, 0.f); v1 = fmaxf(v1, 0.f);
                v2 = fmaxf(v2, 0.f); v3 = fmaxf(v3, 0.f);
            }
            if (Ch) {
                *(__half2*)(Ch + coff + row0 * ldc + col)       = __floats2half2_rn(v0, v1);
                *(__half2*)(Ch + coff + (row0 + 8) * ldc + col) = __floats2half2_rn(v2, v3);
            }
            if (Cf) {
                *(float2*)(Cf + coff + row0 * ldc + col)       = make_float2(v0, v1);
                *(float2*)(Cf + coff + (row0 + 8) * ldc + col) = make_float2(v2, v3);
            }
        }
    }
}

// ------------------------- fused flash attention (fp16) ----------------------
#define BC_   64
#define FSTR  136
#define FLASH_SMEM ((128 * FSTR + 2 * BC_ * FSTR + 2 * BC_ * FSTR) * 2)

__global__ __launch_bounds__(256, 2) void flash_kernel(const __half* __restrict__ qh,
                                                       const __half* __restrict__ kvh,
                                                       const int* __restrict__ cnt,
                                                       __half* __restrict__ ogh)
{
    const int qt  = blockIdx.x;
    const int seg = blockIdx.y >> 2;
    const int h   = blockIdx.y & 3;
    if (qt * 128 >= cnt[seg]) return;
    const int e = seg >> 2;
    const int b = seg & 3;

    extern __shared__ __half fsm[];
    __half* Qs = fsm;
    __half* Ks = fsm + 128 * FSTR;
    __half* Vs = Ks + 2 * BC_ * FSTR;

    const int tid  = threadIdx.x;
    const int lane = tid & 31;
    const int wid  = tid >> 5;
    const float scale = 0.08838834764831845f;

    const __half* qbase = qh + (long long)seg * SD_ + (long long)(qt * 128) * D_ + h * DH_;
    const __half* kbase = kvh + (long long)e * 2 * ND_ + (long long)(b * S_) * D_ + h * DH_;
    const __half* vbase = kbase + ND_;

    {
        int r = tid >> 1, c0 = (tid & 1) * 64;
        const __half* g = qbase + (long long)r * D_ + c0;
        uint32_t s = (uint32_t)__cvta_generic_to_shared(Qs + r * FSTR + c0);
#pragma unroll
        for (int j = 0; j < 8; j++) cp_async16(s + j * 16, g + j * 8);
    }
    {
        int r = tid >> 2, c0 = (tid & 3) * 32;
        const __half* gk = kbase + (long long)r * D_ + c0;
        const __half* gv = vbase + (long long)r * D_ + c0;
        uint32_t sk = (uint32_t)__cvta_generic_to_shared(Ks + r * FSTR + c0);
        uint32_t sv = (uint32_t)__cvta_generic_to_shared(Vs + r * FSTR + c0);
#pragma unroll
        for (int j = 0; j < 4; j++) {
            cp_async16(sk + j * 16, gk + j * 8);
            cp_async16(sv + j * 16, gv + j * 8);
        }
    }
    cp_commit();

    const int r0  = lane >> 2;
    const int qq2 = (lane & 3) * 2;
    const int wrow = wid * 16;

    float oacc[16][4];
#pragma unroll
    for (int i = 0; i < 16; i++)
#pragma unroll
        for (int j = 0; j < 4; j++) oacc[i][j] = 0.f;
    float m0 = -1e30f, m1 = -1e30f, l0 = 0.f, l1 = 0.f;

    const int qRow = wrow + (lane & 15);
    const int qCol = (lane >> 4) << 3;
    const int kRow = lane & 7;
    const int kCol = ((lane >> 3) & 1) << 3;

    for (int t = 0; t < 16; t++) {
        const int st = t & 1;
        cp_wait0();
        __syncthreads();

        if (t < 15) {
            int r = tid >> 2, c0 = (tid & 3) * 32;
            int st2 = st ^ 1;
            const __half* gk = kbase + (long long)((t + 1) * BC_ + r) * D_ + c0;
            const __half* gv = vbase + (long long)((t + 1) * BC_ + r) * D_ + c0;
            uint32_t sk = (uint32_t)__cvta_generic_to_shared(Ks + st2 * BC_ * FSTR + r * FSTR + c0);
            uint32_t sv = (uint32_t)__cvta_generic_to_shared(Vs + st2 * BC_ * FSTR + r * FSTR + c0);
#pragma unroll
            for (int j = 0; j < 4; j++) {
                cp_async16(sk + j * 16, gk + j * 8);
                cp_async16(sv + j * 16, gv + j * 8);
            }
            cp_commit();
        }

        float sacc[8][4];
#pragma unroll
        for (int i = 0; i < 8; i++)
#pragma unroll
            for (int j = 0; j < 4; j++) sacc[i][j] = 0.f;

        const __half* Kt = Ks + st * BC_ * FSTR;
        uint32_t qaddr = (uint32_t)__cvta_generic_to_shared(Qs + qRow * FSTR + qCol);
        uint32_t kaddr = (uint32_t)__cvta_generic_to_shared(Kt + kRow * FSTR + kCol);
#pragma unroll
        for (int ks = 0; ks < 8; ks++) {
            const int kbB = ks * 16 * 2;
            unsigned a0, a1, a2, a3;
            asm volatile(
                "ldmatrix.sync.aligned.m8n8.x4.shared.b16 {%0,%1,%2,%3}, [%4];\n"
                : "=r"(a0), "=r"(a1), "=r"(a2), "=r"(a3)
                : "r"(qaddr + kbB));
#pragma unroll
            for (int ni = 0; ni < 8; ni++) {
                unsigned b0, b1;
                asm volatile(
                    "ldmatrix.sync.aligned.m8n8.x2.shared.b16 {%0,%1}, [%2];\n"
                    : "=r"(b0), "=r"(b1)
                    : "r"(kaddr + kbB + ni * 8 * FSTR * 2));
                mma_f16(sacc[ni], a0, a1, a2, a3, b0, b1);
            }
        }

        float rmax0 = -1e30f, rmax1 = -1e30f;
#pragma unroll
        for (int ni = 0; ni < 8; ni++) {
            sacc[ni][0] *= scale; sacc[ni][1] *= scale;
            sacc[ni][2] *= scale; sacc[ni][3] *= scale;
            rmax0 = fmaxf(rmax0, fmaxf(sacc[ni][0], sacc[ni][1]));
            rmax1 = fmaxf(rmax1, fmaxf(sacc[ni][2], sacc[ni][3]));
        }
        rmax0 = fmaxf(rmax0, __shfl_xor_sync(0xffffffffu, rmax0, 1));
        rmax0 = fmaxf(rmax0, __shfl_xor_sync(0xffffffffu, rmax0, 2));
        rmax1 = fmaxf(rmax1, __shfl_xor_sync(0xffffffffu, rmax1, 1));
        rmax1 = fmaxf(rmax1, __shfl_xor_sync(0xffffffffu, rmax1, 2));
        float mn0 = fmaxf(m0, rmax0), mn1 = fmaxf(m1, rmax1);
        float c0 = __expf(m0 - mn0), c1 = __expf(m1 - mn1);
        m0 = mn0; m1 = mn1;
        float rs0 = 0.f, rs1 = 0.f;
#pragma unroll
        for (int ni = 0; ni < 8; ni++) {
            sacc[ni][0] = __expf(sacc[ni][0] - m0);
            sacc[ni][1] = __expf(sacc[ni][1] - m0);
            sacc[ni][2] = __expf(sacc[ni][2] - m1);
            sacc[ni][3] = __expf(sacc[ni][3] - m1);
            rs0 += sacc[ni][0] + sacc[ni][1];
            rs1 += sacc[ni][2] + sacc[ni][3];
        }
        rs0 += __shfl_xor_sync(0xffffffffu, rs0, 1);
        rs0 += __shfl_xor_sync(0xffffffffu, rs0, 2);
        rs1 += __shfl_xor_sync(0xffffffffu, rs1, 1);
        rs1 += __shfl_xor_sync(0xffffffffu, rs1, 2);
        l0 = l0 * c0 + rs0;
        l1 = l1 * c1 + rs1;
#pragma unroll
        for (int ni = 0; ni < 16; ni++) {
            oacc[ni][0] *= c0; oacc[ni][1] *= c0;
            oacc[ni][2] *= c1; oacc[ni][3] *= c1;
        }

        const __half* Vt = Vs + st * BC_ * FSTR;
#pragma unroll
        for (int ks = 0; ks < 4; ks++) {
            unsigned a0 = h2pack(sacc[2 * ks][0],     sacc[2 * ks][1]);
            unsigned a1 = h2pack(sacc[2 * ks][2],     sacc[2 * ks][3]);
            unsigned a2 = h2pack(sacc[2 * ks + 1][0], sacc[2 * ks + 1][1]);
            unsigned a3 = h2pack(sacc[2 * ks + 1][2], sacc[2 * ks + 1][3]);
            uint32_t vrow = (uint32_t)__cvta_generic_to_shared(
                Vt + (16 * ks + (lane & 15)) * FSTR);
#pragma unroll
            for (int ni = 0; ni < 16; ni++) {
                unsigned b0, b1;
                asm volatile(
                    "ldmatrix.sync.aligned.m8n8.x2.trans.shared.b16 {%0,%1}, [%2];\n"
                    : "=r"(b0), "=r"(b1) : "r"(vrow + ni * 16));
                mma_f16(oacc[ni], a0, a1, a2, a3, b0, b1);
            }
        }
    }

    float inv0 = 1.f / l0, inv1 = 1.f / l1;
    long long row0 = (long long)(qt * 128 + wrow + r0);
    __half* ob = ogh + (long long)seg * SD_ + row0 * D_ + h * DH_;
#pragma unroll
    for (int ni = 0; ni < 16; ni++) {
        int col = ni * 8 + qq2;
        *(__half2*)(ob + col)            = __floats2half2_rn(oacc[ni][0] * inv0, oacc[ni][1] * inv0);
        *(__half2*)(ob + 8LL * D_ + col) = __floats2half2_rn(oacc[ni][2] * inv1, oacc[ni][3] * inv1);
    }
}

// --------------------------- LayerNorm kernels ------------------------------
__global__ void ln1g_kernel(const float* __restrict__ x, const float* __restrict__ t1,
                            const int* __restrict__ idx, const int* __restrict__ cnt,
                            const float* __restrict__ s_all, const float* __restrict__ b_all,
                            float* __restrict__ hg, __half* __restrict__ hgh)
{
    int i   = blockIdx.x;
    int seg = blockIdx.y;
    if (i >= cnt[seg]) return;
    int e = seg >> 2;
    int token = idx[seg * S_ + i];
    const float* a    = x  + (size_t)token * D_;
    const float* bsrc = t1 + ((size_t)seg * S_ + i) * D_;
    const float* s    = s_all + (size_t)e * D_;
    const float* bb   = b_all + (size_t)e * D_;
    float*  outf = hg  + ((size_t)seg * S_ + i) * D_;
    __half* outh = hgh + ((size_t)seg * S_ + i) * D_;
    int t = threadIdx.x;
    __shared__ float red4[4];
    float v[4];
#pragma unroll
    for (int q = 0; q < 4; q++) {
        int d = t + q * 128;
        v[q] = a[d] + bsrc[d];
    }
    float mu = blocksum128(v[0] + v[1] + v[2] + v[3], red4, t) * (1.f / D_);
    float sq = 0.f;
#pragma unroll
    for (int q = 0; q < 4; q++) { float d2 = v[q] - mu; sq += d2 * d2; }
    float inv = rsqrtf(blocksum128(sq, red4, t) * (1.f / D_) + LN_EPS);
#pragma unroll
    for (int q = 0; q < 4; q++) {
        int d = t + q * 128;
        float y = (v[q] - mu) * inv * s[d] + bb[d];
        outf[d] = y;
        outh[d] = __float2half_rn(y);
    }
}

__global__ void ln2_scatter_kernel(const float* __restrict__ hg, const float* __restrict__ f2g,
                                   const float* __restrict__ s_all, const float* __restrict__ b_all,
                                   const float* __restrict__ rw, const int* __restrict__ pos,
                                   float* __restrict__ finalOut)
{
    int n = blockIdx.x;
    int t = threadIdx.x;
    int b = n >> 10;
    __shared__ float red4[4];
    float outv[4] = {0.f, 0.f, 0.f, 0.f};
    for (int e = 0; e < E_; e++) {
        float w = rw[n * E_ + e];
        if (w == 0.f) continue;
        int seg = e * B_ + b;
        int p = pos[n * E_ + e];
        const float* hp = hg  + ((size_t)seg * S_ + p) * D_;
        const float* fp = f2g + ((size_t)seg * S_ + p) * D_;
        const float* s  = s_all + (size_t)e * D_;
        const float* bb = b_all + (size_t)e * D_;
        float v[4];
#pragma unroll
        for (int q = 0; q < 4; q++) {
            int d = t + q * 128;
            v[q] = hp[d] + fp[d];
        }
        float mu = blocksum128(v[0] + v[1] + v[2] + v[3], red4, t) * (1.f / D_);
        float sq = 0.f;
#pragma unroll
        for (int q = 0; q < 4; q++) { float d2 = v[q] - mu; sq += d2 * d2; }
        float inv = rsqrtf(blocksum128(sq, red4, t) * (1.f / D_) + LN_EPS);
#pragma unroll
        for (int q = 0; q < 4; q++) {
            int d = t + q * 128;
            outv[q] += w * ((v[q] - mu) * inv * s[d] + bb[d]);
        }
    }
#pragma unroll
    for (int q = 0; q < 4; q++)
        finalOut[(size_t)n * D_ + t + q * 128] = outv[q];
}

// ------------------------------ host glue -----------------------------------
extern "C" void kernel_launch(void* const* d_in, const int* in_sizes, int n_in,
                              void* d_out, int out_size)
{
    const float* x      = (const float*)d_in[0];
    const float* gate_w = (const float*)d_in[1];
    const float* gate_b = (const float*)d_in[2];
    const float* ln1_s  = (const float*)d_in[3];
    const float* ln1_b  = (const float*)d_in[4];
    const float* ln2_s  = (const float*)d_in[5];
    const float* ln2_b  = (const float*)d_in[6];
    const float* wq     = (const float*)d_in[7];
    const float* wk     = (const float*)d_in[8];
    const float* wv     = (const float*)d_in[9];
    const float* wo     = (const float*)d_in[10];
    const float* bq     = (const float*)d_in[11];
    const float* bk     = (const float*)d_in[12];
    const float* bv     = (const float*)d_in[13];
    const float* bo     = (const float*)d_in[14];
    const float* w1     = (const float*)d_in[15];
    const float* b1     = (const float*)d_in[16];
    const float* w2     = (const float*)d_in[17];
    const float* b2     = (const float*)d_in[18];

    float* out_final  = (float*)d_out;
    float* out_logits = out_final + (size_t)N_ * D_;

    float *rw, *t1, *hg, *f2, *bkv;
    int *cnt, *idx, *pos;
    __half *xh, *wqh, *wkvh, *woh, *w1h, *w2h, *kvh, *qh, *ogh, *hgh, *f1h;
    cudaGetSymbolAddress((void**)&rw,   g_rw);
    cudaGetSymbolAddress((void**)&cnt,  g_cnt);
    cudaGetSymbolAddress((void**)&idx,  g_idx);
    cudaGetSymbolAddress((void**)&pos,  g_pos);
    cudaGetSymbolAddress((void**)&bkv,  g_bkv);
    cudaGetSymbolAddress((void**)&xh,   g_xh);
    cudaGetSymbolAddress((void**)&wqh,  g_wqh);
    cudaGetSymbolAddress((void**)&wkvh, g_wkvh);
    cudaGetSymbolAddress((void**)&woh,  g_woh);
    cudaGetSymbolAddress((void**)&w1h,  g_w1h);
    cudaGetSymbolAddress((void**)&w2h,  g_w2h);
    cudaGetSymbolAddress((void**)&kvh,  g_kvh);
    cudaGetSymbolAddress((void**)&qh,   g_qh);
    cudaGetSymbolAddress((void**)&ogh,  g_ogh);
    cudaGetSymbolAddress((void**)&hgh,  g_hgh);
    cudaGetSymbolAddress((void**)&f1h,  g_f1h);
    cudaGetSymbolAddress((void**)&t1,   g_t1);
    cudaGetSymbolAddress((void**)&hg,   g_hg);
    cudaGetSymbolAddress((void**)&f2,   g_f2);

    static cudaStream_t s_aux = nullptr;
    static cudaEvent_t evFork = nullptr, evJoin = nullptr;
    if (!s_aux) {
        cudaStreamCreateWithFlags(&s_aux, cudaStreamNonBlocking);
        cudaEventCreateWithFlags(&evFork, cudaEventDisableTiming);
        cudaEventCreateWithFlags(&evJoin, cudaEventDisableTiming);
    }

    cudaFuncSetAttribute(flash_kernel,
                         cudaFuncAttributeMaxDynamicSharedMemorySize, FLASH_SMEM);
    cudaFuncSetAttribute(hgemm<false>,
                         cudaFuncAttributeMaxDynamicSharedMemorySize, HGEMM_SMEM);
    cudaFuncSetAttribute(hgemm<true>,
                         cudaFuncAttributeMaxDynamicSharedMemorySize, HGEMM_SMEM);

    // ---- fork: router + gather lists on aux stream ----
    cudaEventRecord(evFork, 0);
    cudaStreamWaitEvent(s_aux, evFork, 0);
    cudaMemsetAsync(cnt, 0, SEGS * sizeof(int), s_aux);
    cudaMemsetAsync(idx, 0, SEGS * S_ * sizeof(int), s_aux);
    router_kernel<<<N_ / 8, 256, 0, s_aux>>>(x, gate_w, gate_b, out_logits, rw);
    build_lists_kernel<<<N_ / 256, 256, 0, s_aux>>>(rw);
    cudaEventRecord(evJoin, s_aux);

    // ---- main stream: conversions + dense K/V GEMM ----
    convall_kernel<<<(int)(UTOT_ / 256), 256>>>(x, wq, wk, wv, wo, w1, w2, bk, bv);

    // K+V projections merged (dense): z = e*2 + {k,v}
    {
        dim3 grid(D_ / 128, N_ / 128, E_ * 2);
        hgemm<false><<<grid, 256, HGEMM_SMEM>>>(
            xh, wkvh, kvh, nullptr, bkv,
            D_, D_, D_, D_,
            2,
            0, 0,
            2LL * DD_, DD_,
            2 * ND_, ND_,
            2LL * D_, D_,
            nullptr, nullptr);
    }

    // ---- join ----
    cudaStreamWaitEvent(0, evJoin, 0);

    // Q projection (gathered): z = seg
    {
        dim3 grid(D_ / 128, S_ / 128, SEGS);
        hgemm<false><<<grid, 256, HGEMM_SMEM>>>(
            xh, wqh, qh, nullptr, bq,
            D_, D_, D_, D_,
            B_,
            0, 0,
            DD_, 0,
            (long long)B_ * SD_, SD_,
            D_, 0,
            cnt, idx);
    }

    // fused attention
    {
        dim3 grid(S_ / 128, SEGS * H_);
        flash_kernel<<<grid, 256, FLASH_SMEM>>>(qh, kvh, cnt, ogh);
    }

    // O projection -> t1 (fp32): z = seg
    {
        dim3 grid(D_ / 128, S_ / 128, SEGS);
        hgemm<false><<<grid, 256, HGEMM_SMEM>>>(
            ogh, woh, nullptr, t1, bo,
            D_, D_, D_, D_,
            B_,
            (long long)B_ * SD_, SD_,
            DD_, 0,
            (long long)B_ * SD_, SD_,
            D_, 0,
            cnt, nullptr);
    }

    // LN1 -> hg (fp32) + hgh (fp16)
    {
        dim3 grid(S_, SEGS);
        ln1g_kernel<<<grid, 128>>>(x, t1, idx, cnt, ln1_s, ln1_b, hg, hgh);
    }

    // FFN1 -> f1h (relu): z = seg
    {
        dim3 grid(F_ / 128, S_ / 128, SEGS);
        hgemm<true><<<grid, 256, HGEMM_SMEM>>>(
            hgh, w1h, f1h, nullptr, b1,
            D_, D_, F_, F_,
            B_,
            (long long)B_ * SD_, SD_,
            (long long)D_ * F_, 0,
            (long long)B_ * SF_, SF_,
            F_, 0,
            cnt, nullptr);
    }

    // FFN2 -> f2 (fp32): z = seg.  NOTE: ldb = D_ (w2 is [F][D] row-major).
    {
        dim3 grid(D_ / 128, S_ / 128, SEGS);
        hgemm<false><<<grid, 256, HGEMM_SMEM>>>(
            f1h, w2h, nullptr, f2, b2,
            F_, F_, D_, D_,
            B_,
            (long long)B_ * SF_, SF_,
            (long long)F_ * D_, 0,
            (long long)B_ * SD_, SD_,
            D_, 0,
            cnt, nullptr);
    }

    // final = sum_e rw * LN2(hg + f2)
    ln2_scatter_kernel<<<N_, 128>>>(hg, f2, ln2_s, ln2_b, rw, pos, out_final);
}

// round 14
// speedup vs baseline: 1.0909x; 1.0047x over previous
#include <cuda_runtime.h>
#include <cuda_fp16.h>
#include <cstdint>

// ---------------------------------------------------------------------------
// SEMMBlock: spiking-router MoE transformer block.
// B=4 S=1024 D=512 E=8 F=2048 H=4 dh=128.
// Round 14: round-13 + hgemm pipeline deepened to 4 stages / wait_group 2
// (two committed cp.async groups always in flight). Everything else identical.
// ---------------------------------------------------------------------------

#define B_  4
#define S_  1024
#define D_  512
#define E_  8
#define F_  2048
#define H_  4
#define DH_ 128
#define N_  (B_ * S_)
#define SEGS (E_ * B_)
#define LN_EPS 1e-5f

#define DD_  (D_ * D_)
#define ND_  ((long long)N_ * D_)
#define SD_  ((long long)S_ * D_)
#define SF_  ((long long)S_ * F_)

// ------------------------- scratch (device globals) ------------------------
__device__ float  g_rw[N_ * E_];
__device__ int    g_cnt[SEGS];
__device__ int    g_idx[SEGS * S_];
__device__ int    g_pos[N_ * E_];
__device__ float  g_bkv[E_ * 2 * D_];
__device__ __half g_xh[N_ * D_];
__device__ __half g_wqh[E_ * DD_];             // [e][K][N] fp16 (untransposed)
__device__ __half g_wkvh[(size_t)E_ * 2 * DD_];// [e][{k,v}][K][N]
__device__ __half g_woh[E_ * DD_];
__device__ __half g_w1h[(size_t)E_ * D_ * F_];
__device__ __half g_w2h[(size_t)E_ * F_ * D_];
__device__ __half g_kvh[(size_t)E_ * 2 * N_ * D_];
__device__ __half g_qh[(size_t)SEGS * S_ * D_];
__device__ __half g_ogh[(size_t)SEGS * S_ * D_];
__device__ __half g_hgh[(size_t)SEGS * S_ * D_];
__device__ __half g_f1h[(size_t)SEGS * S_ * F_];
__device__ float  g_t1[(size_t)SEGS * S_ * D_];
__device__ float  g_hg[(size_t)SEGS * S_ * D_];
__device__ float  g_f2[(size_t)SEGS * S_ * D_];

// ------------------------------ helpers -------------------------------------
__device__ __forceinline__ void cp_async16(uint32_t smem, const void* gptr) {
    asm volatile("cp.async.cg.shared.global [%0], [%1], 16;\n" :: "r"(smem), "l"(gptr));
}
__device__ __forceinline__ void cp_commit() {
    asm volatile("cp.async.commit_group;\n");
}
__device__ __forceinline__ void cp_wait0() {
    asm volatile("cp.async.wait_group 0;\n");
}
__device__ __forceinline__ void cp_wait2() {
    asm volatile("cp.async.wait_group 2;\n");
}
__device__ __forceinline__ void mma_f16(float* c, unsigned a0, unsigned a1,
                                        unsigned a2, unsigned a3,
                                        unsigned b0, unsigned b1) {
    asm volatile(
        "mma.sync.aligned.m16n8k16.row.col.f32.f16.f16.f32 "
        "{%0,%1,%2,%3}, {%4,%5,%6,%7}, {%8,%9}, {%0,%1,%2,%3};\n"
        : "+f"(c[0]), "+f"(c[1]), "+f"(c[2]), "+f"(c[3])
        : "r"(a0), "r"(a1), "r"(a2), "r"(a3), "r"(b0), "r"(b1));
}
__device__ __forceinline__ unsigned h2pack(float x, float y) {
    __half2 h = __floats2half2_rn(x, y);
    return *(unsigned*)&h;
}
__device__ __forceinline__ float blocksum128(float v, float* red4, int t) {
#pragma unroll
    for (int o = 16; o > 0; o >>= 1) v += __shfl_xor_sync(0xffffffffu, v, o);
    if ((t & 31) == 0) red4[t >> 5] = v;
    __syncthreads();
    float s = red4[0] + red4[1] + red4[2] + red4[3];
    __syncthreads();
    return s;
}

// ------------------------------- router -------------------------------------
__global__ void router_kernel(const float* __restrict__ x,
                              const float* __restrict__ gw,
                              const float* __restrict__ gb,
                              float* __restrict__ logits,
                              float* __restrict__ rw)
{
    int warp = (blockIdx.x * blockDim.x + threadIdx.x) >> 5;
    int lane = threadIdx.x & 31;
    if (warp >= N_) return;
    const float* xr = x + (size_t)warp * D_;
    float acc[E_];
#pragma unroll
    for (int e = 0; e < E_; e++) acc[e] = 0.f;
    for (int i = lane; i < D_; i += 32) {
        float xv = xr[i];
        const float* g = gw + i * E_;
#pragma unroll
        for (int e = 0; e < E_; e++) acc[e] += xv * g[e];
    }
#pragma unroll
    for (int e = 0; e < E_; e++) {
#pragma unroll
        for (int o = 16; o > 0; o >>= 1)
            acc[e] += __shfl_down_sync(0xffffffffu, acc[e], o);
    }
    if (lane == 0) {
        float lg[E_];
#pragma unroll
        for (int e = 0; e < E_; e++) {
            lg[e] = acc[e] + gb[e];
            logits[warp * E_ + e] = lg[e];
        }
        int i1 = 0;
#pragma unroll
        for (int e = 1; e < E_; e++) if (lg[e] > lg[i1]) i1 = e;
        int i2 = -1;
#pragma unroll
        for (int e = 0; e < E_; e++) {
            if (e == i1) continue;
            if (i2 < 0 || lg[e] > lg[i2]) i2 = e;
        }
#pragma unroll
        for (int e = 0; e < E_; e++) {
            float r = 0.f;
            if (e == i1 || e == i2) {
                float mem = lg[e] > 0.f ? lg[e] : 0.f;
#pragma unroll
                for (int lvl = 0; lvl < 4; lvl++) {
                    float thr = 4.0f / (float)(1 << lvl);
                    if (mem >= thr) { r += thr; mem -= thr; }
                }
            }
            rw[warp * E_ + e] = r;
        }
    }
}

// -------------------------- build gather lists -------------------------------
__global__ void build_lists_kernel(const float* __restrict__ rw)
{
    int n = blockIdx.x * blockDim.x + threadIdx.x;
    if (n >= N_) return;
    int b = n >> 10;
#pragma unroll
    for (int e = 0; e < E_; e++) {
        if (rw[n * E_ + e] != 0.f) {
            int seg = e * B_ + b;
            int i = atomicAdd(&g_cnt[seg], 1);
            g_idx[seg * S_ + i] = n;
            g_pos[n * E_ + e] = i;
        }
    }
}

// ----------------------------- conversions -----------------------------------
#define U0_ ((long long)N_ * D_ / 8)        // 262144
#define UW_ ((long long)E_ * DD_ / 8)       // 262144
#define UF_ ((long long)E_ * D_ * F_ / 8)   // 1048576
#define UB_ ((long long)E_ * 2 * D_ / 8)    // 1024
#define UTOT_ (U0_ + 4 * UW_ + 2 * UF_ + UB_)

__global__ void convall_kernel(const float* __restrict__ x,  const float* __restrict__ wq,
                               const float* __restrict__ wk, const float* __restrict__ wv,
                               const float* __restrict__ wo, const float* __restrict__ w1,
                               const float* __restrict__ w2,
                               const float* __restrict__ bk, const float* __restrict__ bv)
{
    long long u = (long long)blockIdx.x * blockDim.x + threadIdx.x;
    if (u >= U0_ + 4 * UW_ + 2 * UF_) {     // bias pack segment (float copy)
        long long so = u - (U0_ + 4 * UW_ + 2 * UF_);
        long long gi = so * 8;
        int e = (int)(gi >> 10);
        int r = (int)(gi & 1023);
        int w = r >> 9;
        int d = r & 511;
        const float* s = (w == 0 ? bk : bv) + e * D_ + d;
        *(float4*)(g_bkv + gi)     = *(const float4*)(s);
        *(float4*)(g_bkv + gi + 4) = *(const float4*)(s + 4);
        return;
    }
    const float* src; __half* dst;
    long long so, dofs;
    if (u < U0_)                  { src = x;  dst = g_xh;  so = u;       dofs = so; }
    else if (u < U0_ + UW_)       { src = wq; dst = g_wqh; so = u - U0_; dofs = so; }
    else if (u < U0_ + 2 * UW_)   { so = u - U0_ - UW_;
                                    long long gi = so * 8;
                                    long long e = gi / DD_, r = gi - e * DD_;
                                    src = wk; dst = g_wkvh;
                                    dofs = (e * 2 * DD_ + r) >> 3; }
    else if (u < U0_ + 3 * UW_)   { so = u - U0_ - 2 * UW_;
                                    long long gi = so * 8;
                                    long long e = gi / DD_, r = gi - e * DD_;
                                    src = wv; dst = g_wkvh;
                                    dofs = (e * 2 * DD_ + DD_ + r) >> 3; }
    else if (u < U0_ + 4 * UW_)   { src = wo; dst = g_woh; so = u - U0_ - 3 * UW_; dofs = so; }
    else if (u < U0_ + 4 * UW_ + UF_) { src = w1; dst = g_w1h; so = u - U0_ - 4 * UW_; dofs = so; }
    else                          { src = w2; dst = g_w2h; so = u - U0_ - 4 * UW_ - UF_; dofs = so; }
    long long si = so * 8, di = dofs * 8;
    float4 a = *(const float4*)(src + si);
    float4 b = *(const float4*)(src + si + 4);
    *(__half2*)(dst + di)     = __floats2half2_rn(a.x, a.y);
    *(__half2*)(dst + di + 2) = __floats2half2_rn(a.z, a.w);
    *(__half2*)(dst + di + 4) = __floats2half2_rn(b.x, b.y);
    *(__half2*)(dst + di + 6) = __floats2half2_rn(b.z, b.w);
}

// --------------------------- fp16 tensor GEMM --------------------------------
// C = A[.,K] @ B[K][N] + bias (relu). A fp16 K-major (ldmatrix.x4); B fp16
// untransposed [K][N] (ldmatrix.x2.trans). BM=BN=128, BK=32, 256 thr,
// 8 warps of 64x32. 4-stage cp.async pipeline, wait_group 2.
// Requires K >= 192 (all K here are 512 or 2048).
#define HAPAD 40
#define BSTR  136
#define HGEMM_SMEM (4 * (128 * HAPAD + 32 * BSTR) * 2)

template <bool RELU>
__global__ __launch_bounds__(256, 2) void hgemm(
    const __half* __restrict__ A, const __half* __restrict__ Bp,
    __half* __restrict__ Ch, float* __restrict__ Cf,
    const float* __restrict__ bias,
    int K, int lda, int ldb, int ldc,
    int div1,
    long long sA0, long long sA1,
    long long sB0, long long sB1,
    long long sC0, long long sC1,
    long long sb0, long long sb1,
    const int* __restrict__ mlim, const int* __restrict__ gidx)
{
    const int z  = blockIdx.z;
    const int bm = blockIdx.y * 128;
    if (mlim && bm >= mlim[z]) return;
    const int z0 = z / div1, z1 = z - z0 * div1;
    A  += z0 * sA0 + z1 * sA1;
    Bp += z0 * sB0 + z1 * sB1;
    const long long coff = z0 * sC0 + z1 * sC1;
    const float* biasp = bias + z0 * sb0 + z1 * sb1;

    extern __shared__ __half hsm[];
    __half* As = hsm;                        // [4][128*HAPAD]
    __half* Bs = hsm + 4 * 128 * HAPAD;      // [4][32*BSTR]

    const int tid  = threadIdx.x;
    const int lane = tid & 31;
    const int wid  = tid >> 5;
    const int warpM = (wid >> 2) * 64;
    const int warpN = (wid & 3) * 32;
    const int bn = blockIdx.x * 128;

    const int srow = tid >> 1;
    const int sch  = (tid & 1) * 16;
    long long arow = bm + srow;
    if (gidx) arow = gidx[(long long)z * S_ + arow];
    const __half* gA = A + arow * lda + sch;
    uint32_t sA = (uint32_t)__cvta_generic_to_shared(As + srow * HAPAD + sch);

    const int brow = tid >> 4;
    const int bc16 = (tid & 15) * 8;
    const __half* gB = Bp + (long long)brow * ldb + bn + bc16;
    uint32_t sB = (uint32_t)__cvta_generic_to_shared(Bs + brow * BSTR + bc16);

    const uint32_t stgA = 128 * HAPAD * 2;
    const uint32_t stgB = 32 * BSTR * 2;
    const long long ldb16 = 16LL * ldb;

    float acc[4][4][4];
#pragma unroll
    for (int i = 0; i < 4; i++)
#pragma unroll
        for (int j = 0; j < 4; j++)
#pragma unroll
            for (int q = 0; q < 4; q++) acc[i][j][q] = 0.f;

    // prologue: chunks 0,1,2 -> stages 0,1,2 (three committed groups)
#pragma unroll
    for (int c = 0; c < 3; c++) {
        const __half* gAc = gA + c * 32;
        const __half* gBc = gB + (long long)(c * 32) * ldb;
        cp_async16(sA + c * stgA,      gAc);
        cp_async16(sA + c * stgA + 16, gAc + 8);
        cp_async16(sB + c * stgB,                 gBc);
        cp_async16(sB + c * stgB + 16 * BSTR * 2, gBc + ldb16);
        cp_commit();
    }

    const int qq2 = (lane & 3) * 2;
    const int aRow = warpM + (lane & 15);
    const int aCol = (lane >> 4) << 3;

    int it = 0;
    for (int k0 = 0; k0 < K; k0 += 32, it++) {
        const int st = it & 3;
        cp_wait2();
        __syncthreads();

        if (k0 + 96 < K) {
            const int sp = (it + 3) & 3;
            const __half* gA2 = gA + k0 + 96;
            const __half* gB2 = gB + (long long)(k0 + 96) * ldb;
            cp_async16(sA + sp * stgA,      gA2);
            cp_async16(sA + sp * stgA + 16, gA2 + 8);
            cp_async16(sB + sp * stgB,                 gB2);
            cp_async16(sB + sp * stgB + 16 * BSTR * 2, gB2 + ldb16);
        }
        cp_commit();

        const __half* As0 = As + st * 128 * HAPAD;
        const __half* Bs0 = Bs + st * 32 * BSTR;
        uint32_t aBase = (uint32_t)__cvta_generic_to_shared(As0 + aRow * HAPAD + aCol);

#pragma unroll
        for (int ks = 0; ks < 2; ks++) {
            const int kb = ks * 16;
            unsigned af[4][4], bf[4][2];
#pragma unroll
            for (int mi = 0; mi < 4; mi++) {
                asm volatile(
                    "ldmatrix.sync.aligned.m8n8.x4.shared.b16 {%0,%1,%2,%3}, [%4];\n"
                    : "=r"(af[mi][0]), "=r"(af[mi][1]), "=r"(af[mi][2]), "=r"(af[mi][3])
                    : "r"(aBase + (mi * 16 * HAPAD + kb) * 2));
            }
            uint32_t bbase = (uint32_t)__cvta_generic_to_shared(
                Bs0 + (kb + (lane & 15)) * BSTR + warpN);
#pragma unroll
            for (int ni = 0; ni < 4; ni++) {
                asm volatile(
                    "ldmatrix.sync.aligned.m8n8.x2.trans.shared.b16 {%0,%1}, [%2];\n"
                    : "=r"(bf[ni][0]), "=r"(bf[ni][1]) : "r"(bbase + ni * 16));
            }
#pragma unroll
            for (int mi = 0; mi < 4; mi++)
#pragma unroll
                for (int ni = 0; ni < 4; ni++)
                    mma_f16(acc[mi][ni], af[mi][0], af[mi][1], af[mi][2], af[mi][3],
                            bf[ni][0], bf[ni][1]);
        }
    }

    // epilogue
#pragma unroll
    for (int mi = 0; mi < 4; mi++) {
        long long row0 = bm + warpM + mi * 16 + (lane >> 2);
#pragma unroll
        for (int ni = 0; ni < 4; ni++) {
            int col = bn + warpN + ni * 8 + qq2;
            float b0 = biasp[col], b1 = biasp[col + 1];
            float v0 = acc[mi][ni][0] + b0;
            float v1 = acc[mi][ni][1] + b1;
            float v2 = acc[mi][ni][2] + b0;
            float v3 = acc[mi][ni][3] + b1;
            if (RELU) {
                v0 = fmaxf(v0, 0.f); v1 = fmaxf(v1, 0.f);
                v2 = fmaxf(v2, 0.f); v3 = fmaxf(v3, 0.f);
            }
            if (Ch) {
                *(__half2*)(Ch + coff + row0 * ldc + col)       = __floats2half2_rn(v0, v1);
                *(__half2*)(Ch + coff + (row0 + 8) * ldc + col) = __floats2half2_rn(v2, v3);
            }
            if (Cf) {
                *(float2*)(Cf + coff + row0 * ldc + col)       = make_float2(v0, v1);
                *(float2*)(Cf + coff + (row0 + 8) * ldc + col) = make_float2(v2, v3);
            }
        }
    }
}

// ------------------------- fused flash attention (fp16) ----------------------
#define BC_   64
#define FSTR  136
#define FLASH_SMEM ((128 * FSTR + 2 * BC_ * FSTR + 2 * BC_ * FSTR) * 2)

__global__ __launch_bounds__(256, 2) void flash_kernel(const __half* __restrict__ qh,
                                                       const __half* __restrict__ kvh,
                                                       const int* __restrict__ cnt,
                                                       __half* __restrict__ ogh)
{
    const int qt  = blockIdx.x;
    const int seg = blockIdx.y >> 2;
    const int h   = blockIdx.y & 3;
    if (qt * 128 >= cnt[seg]) return;
    const int e = seg >> 2;
    const int b = seg & 3;

    extern __shared__ __half fsm[];
    __half* Qs = fsm;
    __half* Ks = fsm + 128 * FSTR;
    __half* Vs = Ks + 2 * BC_ * FSTR;

    const int tid  = threadIdx.x;
    const int lane = tid & 31;
    const int wid  = tid >> 5;
    const float scale = 0.08838834764831845f;

    const __half* qbase = qh + (long long)seg * SD_ + (long long)(qt * 128) * D_ + h * DH_;
    const __half* kbase = kvh + (long long)e * 2 * ND_ + (long long)(b * S_) * D_ + h * DH_;
    const __half* vbase = kbase + ND_;

    {
        int r = tid >> 1, c0 = (tid & 1) * 64;
        const __half* g = qbase + (long long)r * D_ + c0;
        uint32_t s = (uint32_t)__cvta_generic_to_shared(Qs + r * FSTR + c0);
#pragma unroll
        for (int j = 0; j < 8; j++) cp_async16(s + j * 16, g + j * 8);
    }
    {
        int r = tid >> 2, c0 = (tid & 3) * 32;
        const __half* gk = kbase + (long long)r * D_ + c0;
        const __half* gv = vbase + (long long)r * D_ + c0;
        uint32_t sk = (uint32_t)__cvta_generic_to_shared(Ks + r * FSTR + c0);
        uint32_t sv = (uint32_t)__cvta_generic_to_shared(Vs + r * FSTR + c0);
#pragma unroll
        for (int j = 0; j < 4; j++) {
            cp_async16(sk + j * 16, gk + j * 8);
            cp_async16(sv + j * 16, gv + j * 8);
        }
    }
    cp_commit();

    const int r0  = lane >> 2;
    const int qq2 = (lane & 3) * 2;
    const int wrow = wid * 16;

    float oacc[16][4];
#pragma unroll
    for (int i = 0; i < 16; i++)
#pragma unroll
        for (int j = 0; j < 4; j++) oacc[i][j] = 0.f;
    float m0 = -1e30f, m1 = -1e30f, l0 = 0.f, l1 = 0.f;

    const int qRow = wrow + (lane & 15);
    const int qCol = (lane >> 4) << 3;
    const int kRow = lane & 7;
    const int kCol = ((lane >> 3) & 1) << 3;

    for (int t = 0; t < 16; t++) {
        const int st = t & 1;
        cp_wait0();
        __syncthreads();

        if (t < 15) {
            int r = tid >> 2, c0 = (tid & 3) * 32;
            int st2 = st ^ 1;
            const __half* gk = kbase + (long long)((t + 1) * BC_ + r) * D_ + c0;
            const __half* gv = vbase + (long long)((t + 1) * BC_ + r) * D_ + c0;
            uint32_t sk = (uint32_t)__cvta_generic_to_shared(Ks + st2 * BC_ * FSTR + r * FSTR + c0);
            uint32_t sv = (uint32_t)__cvta_generic_to_shared(Vs + st2 * BC_ * FSTR + r * FSTR + c0);
#pragma unroll
            for (int j = 0; j < 4; j++) {
                cp_async16(sk + j * 16, gk + j * 8);
                cp_async16(sv + j * 16, gv + j * 8);
            }
            cp_commit();
        }

        float sacc[8][4];
#pragma unroll
        for (int i = 0; i < 8; i++)
#pragma unroll
            for (int j = 0; j < 4; j++) sacc[i][j] = 0.f;

        const __half* Kt = Ks + st * BC_ * FSTR;
        uint32_t qaddr = (uint32_t)__cvta_generic_to_shared(Qs + qRow * FSTR + qCol);
        uint32_t kaddr = (uint32_t)__cvta_generic_to_shared(Kt + kRow * FSTR + kCol);
#pragma unroll
        for (int ks = 0; ks < 8; ks++) {
            const int kbB = ks * 16 * 2;
            unsigned a0, a1, a2, a3;
            asm volatile(
                "ldmatrix.sync.aligned.m8n8.x4.shared.b16 {%0,%1,%2,%3}, [%4];\n"
                : "=r"(a0), "=r"(a1), "=r"(a2), "=r"(a3)
                : "r"(qaddr + kbB));
#pragma unroll
            for (int ni = 0; ni < 8; ni++) {
                unsigned b0, b1;
                asm volatile(
                    "ldmatrix.sync.aligned.m8n8.x2.shared.b16 {%0,%1}, [%2];\n"
                    : "=r"(b0), "=r"(b1)
                    : "r"(kaddr + kbB + ni * 8 * FSTR * 2));
                mma_f16(sacc[ni], a0, a1, a2, a3, b0, b1);
            }
        }

        float rmax0 = -1e30f, rmax1 = -1e30f;
#pragma unroll
        for (int ni = 0; ni < 8; ni++) {
            sacc[ni][0] *= scale; sacc[ni][1] *= scale;
            sacc[ni][2] *= scale; sacc[ni][3] *= scale;
            rmax0 = fmaxf(rmax0, fmaxf(sacc[ni][0], sacc[ni][1]));
            rmax1 = fmaxf(rmax1, fmaxf(sacc[ni][2], sacc[ni][3]));
        }
        rmax0 = fmaxf(rmax0, __shfl_xor_sync(0xffffffffu, rmax0, 1));
        rmax0 = fmaxf(rmax0, __shfl_xor_sync(0xffffffffu, rmax0, 2));
        rmax1 = fmaxf(rmax1, __shfl_xor_sync(0xffffffffu, rmax1, 1));
        rmax1 = fmaxf(rmax1, __shfl_xor_sync(0xffffffffu, rmax1, 2));
        float mn0 = fmaxf(m0, rmax0), mn1 = fmaxf(m1, rmax1);
        float c0 = __expf(m0 - mn0), c1 = __expf(m1 - mn1);
        m0 = mn0; m1 = mn1;
        float rs0 = 0.f, rs1 = 0.f;
#pragma unroll
        for (int ni = 0; ni < 8; ni++) {
            sacc[ni][0] = __expf(sacc[ni][0] - m0);
            sacc[ni][1] = __expf(sacc[ni][1] - m0);
            sacc[ni][2] = __expf(sacc[ni][2] - m1);
            sacc[ni][3] = __expf(sacc[ni][3] - m1);
            rs0 += sacc[ni][0] + sacc[ni][1];
            rs1 += sacc[ni][2] + sacc[ni][3];
        }
        rs0 += __shfl_xor_sync(0xffffffffu, rs0, 1);
        rs0 += __shfl_xor_sync(0xffffffffu, rs0, 2);
        rs1 += __shfl_xor_sync(0xffffffffu, rs1, 1);
        rs1 += __shfl_xor_sync(0xffffffffu, rs1, 2);
        l0 = l0 * c0 + rs0;
        l1 = l1 * c1 + rs1;
#pragma unroll
        for (int ni = 0; ni < 16; ni++) {
            oacc[ni][0] *= c0; oacc[ni][1] *= c0;
            oacc[ni][2] *= c1; oacc[ni][3] *= c1;
        }

        const __half* Vt = Vs + st * BC_ * FSTR;
#pragma unroll
        for (int ks = 0; ks < 4; ks++) {
            unsigned a0 = h2pack(sacc[2 * ks][0],     sacc[2 * ks][1]);
            unsigned a1 = h2pack(sacc[2 * ks][2],     sacc[2 * ks][3]);
            unsigned a2 = h2pack(sacc[2 * ks + 1][0], sacc[2 * ks + 1][1]);
            unsigned a3 = h2pack(sacc[2 * ks + 1][2], sacc[2 * ks + 1][3]);
            uint32_t vrow = (uint32_t)__cvta_generic_to_shared(
                Vt + (16 * ks + (lane & 15)) * FSTR);
#pragma unroll
            for (int ni = 0; ni < 16; ni++) {
                unsigned b0, b1;
                asm volatile(
                    "ldmatrix.sync.aligned.m8n8.x2.trans.shared.b16 {%0,%1}, [%2];\n"
                    : "=r"(b0), "=r"(b1) : "r"(vrow + ni * 16));
                mma_f16(oacc[ni], a0, a1, a2, a3, b0, b1);
            }
        }
    }

    float inv0 = 1.f / l0, inv1 = 1.f / l1;
    long long row0 = (long long)(qt * 128 + wrow + r0);
    __half* ob = ogh + (long long)seg * SD_ + row0 * D_ + h * DH_;
#pragma unroll
    for (int ni = 0; ni < 16; ni++) {
        int col = ni * 8 + qq2;
        *(__half2*)(ob + col)            = __floats2half2_rn(oacc[ni][0] * inv0, oacc[ni][1] * inv0);
        *(__half2*)(ob + 8LL * D_ + col) = __floats2half2_rn(oacc[ni][2] * inv1, oacc[ni][3] * inv1);
    }
}

// --------------------------- LayerNorm kernels ------------------------------
__global__ void ln1g_kernel(const float* __restrict__ x, const float* __restrict__ t1,
                            const int* __restrict__ idx, const int* __restrict__ cnt,
                            const float* __restrict__ s_all, const float* __restrict__ b_all,
                            float* __restrict__ hg, __half* __restrict__ hgh)
{
    int i   = blockIdx.x;
    int seg = blockIdx.y;
    if (i >= cnt[seg]) return;
    int e = seg >> 2;
    int token = idx[seg * S_ + i];
    const float* a    = x  + (size_t)token * D_;
    const float* bsrc = t1 + ((size_t)seg * S_ + i) * D_;
    const float* s    = s_all + (size_t)e * D_;
    const float* bb   = b_all + (size_t)e * D_;
    float*  outf = hg  + ((size_t)seg * S_ + i) * D_;
    __half* outh = hgh + ((size_t)seg * S_ + i) * D_;
    int t = threadIdx.x;
    __shared__ float red4[4];
    float v[4];
#pragma unroll
    for (int q = 0; q < 4; q++) {
        int d = t + q * 128;
        v[q] = a[d] + bsrc[d];
    }
    float mu = blocksum128(v[0] + v[1] + v[2] + v[3], red4, t) * (1.f / D_);
    float sq = 0.f;
#pragma unroll
    for (int q = 0; q < 4; q++) { float d2 = v[q] - mu; sq += d2 * d2; }
    float inv = rsqrtf(blocksum128(sq, red4, t) * (1.f / D_) + LN_EPS);
#pragma unroll
    for (int q = 0; q < 4; q++) {
        int d = t + q * 128;
        float y = (v[q] - mu) * inv * s[d] + bb[d];
        outf[d] = y;
        outh[d] = __float2half_rn(y);
    }
}

__global__ void ln2_scatter_kernel(const float* __restrict__ hg, const float* __restrict__ f2g,
                                   const float* __restrict__ s_all, const float* __restrict__ b_all,
                                   const float* __restrict__ rw, const int* __restrict__ pos,
                                   float* __restrict__ finalOut)
{
    int n = blockIdx.x;
    int t = threadIdx.x;
    int b = n >> 10;
    __shared__ float red4[4];
    float outv[4] = {0.f, 0.f, 0.f, 0.f};
    for (int e = 0; e < E_; e++) {
        float w = rw[n * E_ + e];
        if (w == 0.f) continue;
        int seg = e * B_ + b;
        int p = pos[n * E_ + e];
        const float* hp = hg  + ((size_t)seg * S_ + p) * D_;
        const float* fp = f2g + ((size_t)seg * S_ + p) * D_;
        const float* s  = s_all + (size_t)e * D_;
        const float* bb = b_all + (size_t)e * D_;
        float v[4];
#pragma unroll
        for (int q = 0; q < 4; q++) {
            int d = t + q * 128;
            v[q] = hp[d] + fp[d];
        }
        float mu = blocksum128(v[0] + v[1] + v[2] + v[3], red4, t) * (1.f / D_);
        float sq = 0.f;
#pragma unroll
        for (int q = 0; q < 4; q++) { float d2 = v[q] - mu; sq += d2 * d2; }
        float inv = rsqrtf(blocksum128(sq, red4, t) * (1.f / D_) + LN_EPS);
#pragma unroll
        for (int q = 0; q < 4; q++) {
            int d = t + q * 128;
            outv[q] += w * ((v[q] - mu) * inv * s[d] + bb[d]);
        }
    }
#pragma unroll
    for (int q = 0; q < 4; q++)
        finalOut[(size_t)n * D_ + t + q * 128] = outv[q];
}

// ------------------------------ host glue -----------------------------------
extern "C" void kernel_launch(void* const* d_in, const int* in_sizes, int n_in,
                              void* d_out, int out_size)
{
    const float* x      = (const float*)d_in[0];
    const float* gate_w = (const float*)d_in[1];
    const float* gate_b = (const float*)d_in[2];
    const float* ln1_s  = (const float*)d_in[3];
    const float* ln1_b  = (const float*)d_in[4];
    const float* ln2_s  = (const float*)d_in[5];
    const float* ln2_b  = (const float*)d_in[6];
    const float* wq     = (const float*)d_in[7];
    const float* wk     = (const float*)d_in[8];
    const float* wv     = (const float*)d_in[9];
    const float* wo     = (const float*)d_in[10];
    const float* bq     = (const float*)d_in[11];
    const float* bk     = (const float*)d_in[12];
    const float* bv     = (const float*)d_in[13];
    const float* bo     = (const float*)d_in[14];
    const float* w1     = (const float*)d_in[15];
    const float* b1     = (const float*)d_in[16];
    const float* w2     = (const float*)d_in[17];
    const float* b2     = (const float*)d_in[18];

    float* out_final  = (float*)d_out;
    float* out_logits = out_final + (size_t)N_ * D_;

    float *rw, *t1, *hg, *f2, *bkv;
    int *cnt, *idx, *pos;
    __half *xh, *wqh, *wkvh, *woh, *w1h, *w2h, *kvh, *qh, *ogh, *hgh, *f1h;
    cudaGetSymbolAddress((void**)&rw,   g_rw);
    cudaGetSymbolAddress((void**)&cnt,  g_cnt);
    cudaGetSymbolAddress((void**)&idx,  g_idx);
    cudaGetSymbolAddress((void**)&pos,  g_pos);
    cudaGetSymbolAddress((void**)&bkv,  g_bkv);
    cudaGetSymbolAddress((void**)&xh,   g_xh);
    cudaGetSymbolAddress((void**)&wqh,  g_wqh);
    cudaGetSymbolAddress((void**)&wkvh, g_wkvh);
    cudaGetSymbolAddress((void**)&woh,  g_woh);
    cudaGetSymbolAddress((void**)&w1h,  g_w1h);
    cudaGetSymbolAddress((void**)&w2h,  g_w2h);
    cudaGetSymbolAddress((void**)&kvh,  g_kvh);
    cudaGetSymbolAddress((void**)&qh,   g_qh);
    cudaGetSymbolAddress((void**)&ogh,  g_ogh);
    cudaGetSymbolAddress((void**)&hgh,  g_hgh);
    cudaGetSymbolAddress((void**)&f1h,  g_f1h);
    cudaGetSymbolAddress((void**)&t1,   g_t1);
    cudaGetSymbolAddress((void**)&hg,   g_hg);
    cudaGetSymbolAddress((void**)&f2,   g_f2);

    static cudaStream_t s_aux = nullptr;
    static cudaEvent_t evFork = nullptr, evJoin = nullptr;
    if (!s_aux) {
        cudaStreamCreateWithFlags(&s_aux, cudaStreamNonBlocking);
        cudaEventCreateWithFlags(&evFork, cudaEventDisableTiming);
        cudaEventCreateWithFlags(&evJoin, cudaEventDisableTiming);
    }

    cudaFuncSetAttribute(flash_kernel,
                         cudaFuncAttributeMaxDynamicSharedMemorySize, FLASH_SMEM);
    cudaFuncSetAttribute(hgemm<false>,
                         cudaFuncAttributeMaxDynamicSharedMemorySize, HGEMM_SMEM);
    cudaFuncSetAttribute(hgemm<true>,
                         cudaFuncAttributeMaxDynamicSharedMemorySize, HGEMM_SMEM);

    // ---- fork: router + gather lists on aux stream ----
    cudaEventRecord(evFork, 0);
    cudaStreamWaitEvent(s_aux, evFork, 0);
    cudaMemsetAsync(cnt, 0, SEGS * sizeof(int), s_aux);
    cudaMemsetAsync(idx, 0, SEGS * S_ * sizeof(int), s_aux);
    router_kernel<<<N_ / 8, 256, 0, s_aux>>>(x, gate_w, gate_b, out_logits, rw);
    build_lists_kernel<<<N_ / 256, 256, 0, s_aux>>>(rw);
    cudaEventRecord(evJoin, s_aux);

    // ---- main stream: conversions + dense K/V GEMM ----
    convall_kernel<<<(int)(UTOT_ / 256), 256>>>(x, wq, wk, wv, wo, w1, w2, bk, bv);

    // K+V projections merged (dense): z = e*2 + {k,v}
    {
        dim3 grid(D_ / 128, N_ / 128, E_ * 2);
        hgemm<false><<<grid, 256, HGEMM_SMEM>>>(
            xh, wkvh, kvh, nullptr, bkv,
            D_, D_, D_, D_,
            2,
            0, 0,
            2LL * DD_, DD_,
            2 * ND_, ND_,
            2LL * D_, D_,
            nullptr, nullptr);
    }

    // ---- join ----
    cudaStreamWaitEvent(0, evJoin, 0);

    // Q projection (gathered): z = seg
    {
        dim3 grid(D_ / 128, S_ / 128, SEGS);
        hgemm<false><<<grid, 256, HGEMM_SMEM>>>(
            xh, wqh, qh, nullptr, bq,
            D_, D_, D_, D_,
            B_,
            0, 0,
            DD_, 0,
            (long long)B_ * SD_, SD_,
            D_, 0,
            cnt, idx);
    }

    // fused attention
    {
        dim3 grid(S_ / 128, SEGS * H_);
        flash_kernel<<<grid, 256, FLASH_SMEM>>>(qh, kvh, cnt, ogh);
    }

    // O projection -> t1 (fp32): z = seg
    {
        dim3 grid(D_ / 128, S_ / 128, SEGS);
        hgemm<false><<<grid, 256, HGEMM_SMEM>>>(
            ogh, woh, nullptr, t1, bo,
            D_, D_, D_, D_,
            B_,
            (long long)B_ * SD_, SD_,
            DD_, 0,
            (long long)B_ * SD_, SD_,
            D_, 0,
            cnt, nullptr);
    }

    // LN1 -> hg (fp32) + hgh (fp16)
    {
        dim3 grid(S_, SEGS);
        ln1g_kernel<<<grid, 128>>>(x, t1, idx, cnt, ln1_s, ln1_b, hg, hgh);
    }

    // FFN1 -> f1h (relu): z = seg
    {
        dim3 grid(F_ / 128, S_ / 128, SEGS);
        hgemm<true><<<grid, 256, HGEMM_SMEM>>>(
            hgh, w1h, f1h, nullptr, b1,
            D_, D_, F_, F_,
            B_,
            (long long)B_ * SD_, SD_,
            (long long)D_ * F_, 0,
            (long long)B_ * SF_, SF_,
            F_, 0,
            cnt, nullptr);
    }

    // FFN2 -> f2 (fp32): z = seg. ldb = D_ (w2 is [F][D] row-major).
    {
        dim3 grid(D_ / 128, S_ / 128, SEGS);
        hgemm<false><<<grid, 256, HGEMM_SMEM>>>(
            f1h, w2h, nullptr, f2, b2,
            F_, F_, D_, D_,
            B_,
            (long long)B_ * SF_, SF_,
            (long long)F_ * D_, 0,
            (long long)B_ * SD_, SD_,
            D_, 0,
            cnt, nullptr);
    }

    // final = sum_e rw * LN2(hg + f2)
    ln2_scatter_kernel<<<N_, 128>>>(hg, f2, ln2_s, ln2_b, rw, pos, out_final);
}